// round 13
// baseline (speedup 1.0000x reference)
#include <cuda_runtime.h>
#include <cuda_bf16.h>
#include <cuda_fp16.h>
#include <math.h>
#include <stdint.h>

#define Dm    1024
#define SEQn  512
#define NB    2
#define NH    16
#define DHd   64
#define DFFn  2730
#define DFFP  2816
#define NV    32000
#define NL    4
#define MT    1024
#define NQKV  3072
#define NHG   5632
#define UD    512
#define UF    1408
#define NCKD  16
#define NCKF  44

#define GDC_WAIT()   asm volatile("griddepcontrol.wait;" ::: "memory")
#define GDC_LAUNCH() asm volatile("griddepcontrol.launch_dependents;" ::: "memory")

// ---------------- fp32 scratch ----------------
__device__ float g_x[MT*Dm];
__device__ float g_qkv[MT*NQKV];
__device__ float g_obuf[MT*Dm];
__device__ float g_v0h[NB*NH*SEQn*DHd];
__device__ float g_fo[NL*Dm];
__device__ float g_fffo[NL*DFFn];
__device__ float g_part[8*NL*DFFP];

// ---------------- packed fp16 buffers, chunked pre-swizzled layout ----------------
__device__ uint32_t g_xp2 [MT*UD];
__device__ uint32_t g_op2 [MT*UD];
__device__ uint32_t g_zp2 [MT*UF];
__device__ uint32_t g_wqkv2[(size_t)NL*NQKV*UD];
__device__ uint32_t g_wo2  [(size_t)NL*Dm*UD];
__device__ uint32_t g_whg2 [(size_t)NL*NHG*UD];
__device__ uint32_t g_wfo2 [(size_t)NL*Dm*UF];
__device__ uint32_t g_wl2  [(size_t)NV*UD];

static __device__ __forceinline__ size_t cidx(int gr, int j, int ncK){
    return ((size_t)(gr>>7)*ncK + (j>>5))*4096 + (size_t)(gr&127)*32
         + ((((j>>2)&7) ^ (gr&7))<<2) + (j&3);
}

// ---------------- scalar helpers ----------------
static __device__ __forceinline__ float l2fac(float n){
    float tgt = fminf(fmaxf(n, 1.0f - 1e-5f), 1.0f + 1e-5f);
    return 1.0f / fmaxf(n / tgt, 1e-10f);
}
static __device__ __forceinline__ float warpsum(float v){
    #pragma unroll
    for(int o=16;o>0;o>>=1) v += __shfl_xor_sync(0xffffffffu, v, o);
    return v;
}
static __device__ __forceinline__ float blocksum256(float v, float* red){
    red[threadIdx.x] = v; __syncthreads();
    for(int o=128;o>0;o>>=1){
        if(threadIdx.x < o) red[threadIdx.x] += red[threadIdx.x+o];
        __syncthreads();
    }
    float r = red[0]; __syncthreads();
    return r;
}
static __device__ __forceinline__ uint32_t packh2(float x0, float x1){
    return (uint32_t)__half_as_ushort(__float2half_rn(x0))
         | ((uint32_t)__half_as_ushort(__float2half_rn(x1))<<16);
}

// ---------------- bulk-copy / mbarrier / ldmatrix / mma primitives ----------------
static __device__ __forceinline__ void mbar_init(uint32_t a, uint32_t c){
    asm volatile("mbarrier.init.shared.b64 [%0], %1;" :: "r"(a), "r"(c) : "memory");
}
static __device__ __forceinline__ void mbar_expect(uint32_t a, uint32_t bytes){
    asm volatile("mbarrier.arrive.expect_tx.shared.b64 _, [%0], %1;"
                 :: "r"(a), "r"(bytes) : "memory");
}
static __device__ __forceinline__ void mbar_wait(uint32_t a, uint32_t ph){
    asm volatile("{\n\t.reg .pred P;\n\t"
        "WL_%=:\n\t"
        "mbarrier.try_wait.parity.shared.b64 P, [%0], %1;\n\t"
        "@P bra.uni WD_%=;\n\t"
        "bra.uni WL_%=;\n\t"
        "WD_%=:\n\t}"
        :: "r"(a), "r"(ph) : "memory");
}
static __device__ __forceinline__ void bulkcp(uint32_t dst, const void* src, uint32_t bytes,
                                              uint32_t mbar){
    asm volatile("cp.async.bulk.shared::cluster.global.mbarrier::complete_tx::bytes "
                 "[%0], [%1], %2, [%3];"
                 :: "r"(dst), "l"(src), "r"(bytes), "r"(mbar) : "memory");
}
static __device__ __forceinline__ void ldsm4(uint32_t* r, uint32_t a){
    asm volatile("ldmatrix.sync.aligned.m8n8.x4.shared.b16 {%0,%1,%2,%3}, [%4];"
        : "=r"(r[0]),"=r"(r[1]),"=r"(r[2]),"=r"(r[3]) : "r"(a));
}
static __device__ __forceinline__ void mma_f16(float* c,
        uint32_t a0, uint32_t a1, uint32_t a2, uint32_t a3, uint32_t b0, uint32_t b1){
    asm volatile("mma.sync.aligned.m16n8k16.row.col.f32.f16.f16.f32 "
                 "{%0,%1,%2,%3},{%4,%5,%6,%7},{%8,%9},{%0,%1,%2,%3};"
                 : "+f"(c[0]), "+f"(c[1]), "+f"(c[2]), "+f"(c[3])
                 : "r"(a0), "r"(a1), "r"(a2), "r"(a3), "r"(b0), "r"(b1));
}

// ---------------- bulk-copy mma GEMM: C[M,N] = A @ B^T (fp32 out) ----------------
template<int BM,int BN,int WM,int WN,int S,int EPI>
__global__ void __launch_bounds__(256, 2)
gemm_mma_k(const uint32_t* __restrict__ Au, const uint32_t* __restrict__ Bu,
           void* __restrict__ Cv, int ldc, int Ks){
    constexpr int ABYTES = BM*128, BBYTES = BN*128, STAGE = ABYTES+BBYTES;
    constexpr int WNW = BN/WN;
    constexpr int MI = WM/16, NJ = WN/8, NJ2 = NJ/2;

    extern __shared__ char sm[];
    uint32_t smBase = (uint32_t)__cvta_generic_to_shared(sm);
    uint32_t mb = smBase;
    uint32_t tiles = smBase + 1024;

    const int tid = threadIdx.x, warp = tid>>5, lane = tid&31;
    const int wm = warp / WNW, wn = warp % WNW;
    const int i8 = lane&7, sub = lane>>3;
    const int g = lane>>2, t4 = lane&3;
    const int rowBase = blockIdx.x*BM, colBase = blockIdx.y*BN;
    const int NC = Ks>>6;

    const char* AbBase = (const char*)Au + ((size_t)(rowBase>>7)*NC)*16384
                       + (size_t)((rowBase>>6)&1)*8192;
    const char* BbBase = (const char*)Bu + ((size_t)(colBase>>7)*NC)*16384
                       + (size_t)((colBase>>6)&1)*8192;

    if(tid==0){
        #pragma unroll
        for(int s=0;s<S;s++) mbar_init(mb + 8*s, 1);
    }
    __syncthreads();
    GDC_WAIT();
    if(tid==0){
        #pragma unroll
        for(int s=0;s<S-1;s++){
            mbar_expect(mb + 8*s, STAGE);
            bulkcp(tiles + s*STAGE,          AbBase + (size_t)s*16384, ABYTES, mb + 8*s);
            bulkcp(tiles + s*STAGE + ABYTES, BbBase + (size_t)s*16384, BBYTES, mb + 8*s);
        }
    }

    const int cA = sub>>1, cB = sub&1;
    uint32_t aRow[MI], bRow[NJ2];
    #pragma unroll
    for(int it=0;it<MI;it++)
        aRow[it] = tiles + (uint32_t)((wm*WM + it*16 + (sub&1)*8 + i8)*128);
    #pragma unroll
    for(int jp=0;jp<NJ2;jp++)
        bRow[jp] = tiles + (uint32_t)(ABYTES + (wn*WN + jp*16 + (sub>>1)*8 + i8)*128);

    float acc[MI][NJ][4];
    #pragma unroll
    for(int i=0;i<MI;i++)
        #pragma unroll
        for(int j=0;j<NJ;j++)
            #pragma unroll
            for(int e=0;e<4;e++) acc[i][j][e] = 0.0f;

    uint32_t ahB[2][MI][4], bbB[2][NJ2][4];

    for(int c=0;c<NC;c++){
        int s = c % S;
        mbar_wait(mb + 8*s, (uint32_t)((c/S)&1));
        if(tid==0 && c+S-1 < NC){
            int s2 = (c+S-1)%S;
            mbar_expect(mb + 8*s2, STAGE);
            bulkcp(tiles + s2*STAGE,          AbBase + (size_t)(c+S-1)*16384, ABYTES, mb + 8*s2);
            bulkcp(tiles + s2*STAGE + ABYTES, BbBase + (size_t)(c+S-1)*16384, BBYTES, mb + 8*s2);
        }
        const uint32_t bufOff = (uint32_t)(s*STAGE);

        #define LD_FRAG(kk, p) do{                                                   \
            _Pragma("unroll")                                                        \
            for(int it_=0;it_<MI;it_++)                                              \
                ldsm4(ahB[p][it_], aRow[it_] + bufOff + (uint32_t)((((2*(kk) + cA) ^ i8))<<4)); \
            _Pragma("unroll")                                                        \
            for(int jp_=0;jp_<NJ2;jp_++)                                             \
                ldsm4(bbB[p][jp_], bRow[jp_] + bufOff + (uint32_t)((((2*(kk) + cB) ^ i8))<<4)); \
        }while(0)

        LD_FRAG(0, 0);
        #pragma unroll
        for(int kk=0;kk<4;kk++){
            const int cur = kk&1;
            if(kk<3) LD_FRAG(kk+1, cur^1);
            #pragma unroll
            for(int it=0;it<MI;it++)
                #pragma unroll
                for(int jt=0;jt<NJ;jt++){
                    const uint32_t* bf = bbB[cur][jt>>1];
                    int o = (jt&1)*2;
                    mma_f16(acc[it][jt], ahB[cur][it][0], ahB[cur][it][1],
                            ahB[cur][it][2], ahB[cur][it][3], bf[o], bf[o+1]);
                }
        }
        #undef LD_FRAG
        __syncthreads();
    }
    GDC_LAUNCH();

    float* C = (float*)Cv;
    #pragma unroll
    for(int jt=0;jt<NJ;jt++){
        int c = colBase + wn*WN + jt*8 + t4*2;
        #pragma unroll
        for(int it=0;it<MI;it++){
            int r = rowBase + wm*WM + it*16 + g;
            *(float2*)(C + (size_t)r*ldc + c)     = make_float2(acc[it][jt][0], acc[it][jt][1]);
            *(float2*)(C + (size_t)(r+8)*ldc + c) = make_float2(acc[it][jt][2], acc[it][jt][3]);
        }
    }
}

// hg GEMM: (h,g) col pairs -> packed fp16 silu(g)*h into chunked C
template<int BM,int BN,int WM,int WN,int S>
__global__ void __launch_bounds__(256, 2)
gemm_hg_k(const uint32_t* __restrict__ Au, const uint32_t* __restrict__ Bu,
          uint32_t* __restrict__ Cv, int ncK, int Ks){
    constexpr int ABYTES = BM*128, BBYTES = BN*128, STAGE = ABYTES+BBYTES;
    constexpr int WNW = BN/WN;
    constexpr int MI = WM/16, NJ = WN/8, NJ2 = NJ/2;

    extern __shared__ char sm[];
    uint32_t smBase = (uint32_t)__cvta_generic_to_shared(sm);
    uint32_t mb = smBase;
    uint32_t tiles = smBase + 1024;

    const int tid = threadIdx.x, warp = tid>>5, lane = tid&31;
    const int wm = warp / WNW, wn = warp % WNW;
    const int i8 = lane&7, sub = lane>>3;
    const int g = lane>>2, t4 = lane&3;
    const int rowBase = blockIdx.x*BM, colBase = blockIdx.y*BN;
    const int NC = Ks>>6;

    const char* AbBase = (const char*)Au + ((size_t)(rowBase>>7)*NC)*16384
                       + (size_t)((rowBase>>6)&1)*8192;
    const char* BbBase = (const char*)Bu + ((size_t)(colBase>>7)*NC)*16384
                       + (size_t)((colBase>>6)&1)*8192;

    if(tid==0){
        #pragma unroll
        for(int s=0;s<S;s++) mbar_init(mb + 8*s, 1);
    }
    __syncthreads();
    GDC_WAIT();
    if(tid==0){
        #pragma unroll
        for(int s=0;s<S-1;s++){
            mbar_expect(mb + 8*s, STAGE);
            bulkcp(tiles + s*STAGE,          AbBase + (size_t)s*16384, ABYTES, mb + 8*s);
            bulkcp(tiles + s*STAGE + ABYTES, BbBase + (size_t)s*16384, BBYTES, mb + 8*s);
        }
    }

    const int cA = sub>>1, cB = sub&1;
    uint32_t aRow[MI], bRow[NJ2];
    #pragma unroll
    for(int it=0;it<MI;it++)
        aRow[it] = tiles + (uint32_t)((wm*WM + it*16 + (sub&1)*8 + i8)*128);
    #pragma unroll
    for(int jp=0;jp<NJ2;jp++)
        bRow[jp] = tiles + (uint32_t)(ABYTES + (wn*WN + jp*16 + (sub>>1)*8 + i8)*128);

    float acc[MI][NJ][4];
    #pragma unroll
    for(int i=0;i<MI;i++)
        #pragma unroll
        for(int j=0;j<NJ;j++)
            #pragma unroll
            for(int e=0;e<4;e++) acc[i][j][e] = 0.0f;

    uint32_t ahB[2][MI][4], bbB[2][NJ2][4];

    for(int c=0;c<NC;c++){
        int s = c % S;
        mbar_wait(mb + 8*s, (uint32_t)((c/S)&1));
        if(tid==0 && c+S-1 < NC){
            int s2 = (c+S-1)%S;
            mbar_expect(mb + 8*s2, STAGE);
            bulkcp(tiles + s2*STAGE,          AbBase + (size_t)(c+S-1)*16384, ABYTES, mb + 8*s2);
            bulkcp(tiles + s2*STAGE + ABYTES, BbBase + (size_t)(c+S-1)*16384, BBYTES, mb + 8*s2);
        }
        const uint32_t bufOff = (uint32_t)(s*STAGE);

        #define LD_FRAG(kk, p) do{                                                   \
            _Pragma("unroll")                                                        \
            for(int it_=0;it_<MI;it_++)                                              \
                ldsm4(ahB[p][it_], aRow[it_] + bufOff + (uint32_t)((((2*(kk) + cA) ^ i8))<<4)); \
            _Pragma("unroll")                                                        \
            for(int jp_=0;jp_<NJ2;jp_++)                                             \
                ldsm4(bbB[p][jp_], bRow[jp_] + bufOff + (uint32_t)((((2*(kk) + cB) ^ i8))<<4)); \
        }while(0)

        LD_FRAG(0, 0);
        #pragma unroll
        for(int kk=0;kk<4;kk++){
            const int cur = kk&1;
            if(kk<3) LD_FRAG(kk+1, cur^1);
            #pragma unroll
            for(int it=0;it<MI;it++)
                #pragma unroll
                for(int jt=0;jt<NJ;jt++){
                    const uint32_t* bf = bbB[cur][jt>>1];
                    int o = (jt&1)*2;
                    mma_f16(acc[it][jt], ahB[cur][it][0], ahB[cur][it][1],
                            ahB[cur][it][2], ahB[cur][it][3], bf[o], bf[o+1]);
                }
        }
        #undef LD_FRAG
        __syncthreads();
    }
    GDC_LAUNCH();

    #pragma unroll
    for(int jt=0;jt<NJ;jt++){
        int i0 = ((colBase + wn*WN + jt*8)>>1) + t4;
        #pragma unroll
        for(int it=0;it<MI;it++){
            int r = rowBase + wm*WM + it*16 + g;
            float h0 = acc[it][jt][0], g0 = acc[it][jt][1];
            float h1 = acc[it][jt][2], g1 = acc[it][jt][3];
            float z0 = g0/(1.0f + __expf(-g0))*h0;
            float z1 = g1/(1.0f + __expf(-g1))*h1;
            float z0n = __shfl_xor_sync(0xffffffffu, z0, 1);
            float z1n = __shfl_xor_sync(0xffffffffu, z1, 1);
            if((t4 & 1) == 0){
                int j = i0>>1;
                Cv[cidx(r,   j, ncK)] = packh2(z0, z0n);
                Cv[cidx(r+8, j, ncK)] = packh2(z1, z1n);
            }
        }
    }
}

// ---------------- split column norms: 8-way row partials + finalize ----------------
__global__ void colnorm_part_k(const float* __restrict__ W, float* __restrict__ part,
                               int R, int C){
    int l = blockIdx.y;
    int c = blockIdx.x*256 + threadIdx.x;
    int sp = blockIdx.z;
    if(c >= C) return;
    const float* Wl = W + (size_t)l*R*C;
    int r0 = sp*(R>>3), r1 = r0 + (R>>3);
    float s = 0.0f;
    for(int r=r0;r<r1;r++){ float w = Wl[(size_t)r*C + c]; s += w*w; }
    part[((size_t)sp*NL + l)*DFFP + c] = s;
}
__global__ void colnorm_fin_k(const float* __restrict__ part, float* __restrict__ f, int C){
    int l = blockIdx.y;
    int c = blockIdx.x*256 + threadIdx.x;
    if(c >= C) return;
    float s = 0.0f;
    #pragma unroll
    for(int sp=0;sp<8;sp++) s += part[((size_t)sp*NL + l)*DFFP + c];
    f[(size_t)l*C + c] = l2fac(sqrtf(s));
}

// ---------------- fused norm + pack kernels ----------------
__global__ void wpack_qkv_k(const float* __restrict__ Wq, const float* __restrict__ Wk,
                            const float* __restrict__ Wv, int lbase,
                            uint32_t* __restrict__ dst){
    __shared__ float red[256];
    int rr = blockIdx.x + lbase*NQKV;
    int l = rr / NQKV, r = rr % NQKV;
    int which = r >> 10, rl = r & 1023;
    const float* W = (which==0) ? Wq : (which==1) ? Wk : Wv;
    const float4* sp = (const float4*)(W + ((size_t)l*Dm + rl)*Dm);
    float4 v = sp[threadIdx.x];
    float s = v.x*v.x + v.y*v.y + v.z*v.z + v.w*v.w;
    s = blocksum256(s, red);
    float f = l2fac(sqrtf(s));
    dst[cidx(rr, 2*threadIdx.x,   NCKD)] = packh2(v.x*f, v.y*f);
    dst[cidx(rr, 2*threadIdx.x+1, NCKD)] = packh2(v.z*f, v.w*f);
}
__global__ void wpack_o_k(const float* __restrict__ Wo, uint32_t* __restrict__ dst){
    int rr = blockIdx.x;
    const float4* sp = (const float4*)(Wo + (size_t)rr*Dm);
    float4 v = sp[threadIdx.x];
    dst[cidx(rr, 2*threadIdx.x,   NCKD)] = packh2(v.x, v.y);
    dst[cidx(rr, 2*threadIdx.x+1, NCKD)] = packh2(v.z, v.w);
}
__global__ void wpack_hg_k(const float* __restrict__ Wffh, const float* __restrict__ Wffg,
                           const float* __restrict__ hsc, const float* __restrict__ gsc,
                           uint32_t* __restrict__ dst){
    __shared__ float red[256];
    int rr = blockIdx.x;
    int l = rr / NHG, r = rr % NHG;
    int p = r >> 1, isG = r & 1;
    if(p >= DFFn){
        dst[cidx(rr, 2*threadIdx.x,   NCKD)] = 0u;
        dst[cidx(rr, 2*threadIdx.x+1, NCKD)] = 0u;
        return;
    }
    size_t sr = (size_t)l*DFFn + p;
    const float* W = isG ? (Wffg + sr*Dm) : (Wffh + sr*Dm);
    float sc = isG ? gsc[sr]*32.0f : hsc[sr];
    float4 v = ((const float4*)W)[threadIdx.x];
    float s = v.x*v.x + v.y*v.y + v.z*v.z + v.w*v.w;
    s = blocksum256(s, red);
    float f = l2fac(sqrtf(s))*sc;
    dst[cidx(rr, 2*threadIdx.x,   NCKD)] = packh2(v.x*f, v.y*f);
    dst[cidx(rr, 2*threadIdx.x+1, NCKD)] = packh2(v.z*f, v.w*f);
}
__global__ void wpack_fo_k(const float* __restrict__ Wffo, const float* __restrict__ fffo,
                           uint32_t* __restrict__ dst){
    int rr = blockIdx.x;
    int l = rr / Dm, rl = rr % Dm;
    const float2* sp = (const float2*)(Wffo + ((size_t)l*Dm + rl)*DFFn);
    const float* ks = fffo + (size_t)l*DFFn;
    for(int j=threadIdx.x;j<UF;j+=256){
        float x0=0.0f, x1=0.0f;
        if(2*j < DFFn){ float2 vv = sp[j]; x0 = vv.x*ks[2*j]; x1 = vv.y*ks[2*j+1]; }
        dst[cidx(rr, j, NCKF)] = packh2(x0, x1);
    }
}
__global__ void wpack_log_k(const float* __restrict__ Wl, const float* __restrict__ lsc,
                            uint32_t* __restrict__ dst){
    __shared__ float red[256];
    int r = blockIdx.x;
    const float4* sp = (const float4*)(Wl + (size_t)r*Dm);
    float4 v = sp[threadIdx.x];
    float s = v.x*v.x + v.y*v.y + v.z*v.z + v.w*v.w;
    s = blocksum256(s, red);
    float f = l2fac(sqrtf(s))*lsc[r]*32.0f;
    dst[cidx(r, 2*threadIdx.x,   NCKD)] = packh2(v.x*f, v.y*f);
    dst[cidx(r, 2*threadIdx.x+1, NCKD)] = packh2(v.z*f, v.w*f);
}

// ---------------- embedding ----------------
__global__ void embed_k(const int* __restrict__ ids, const float* __restrict__ W_emb,
                        float* __restrict__ x, uint32_t* __restrict__ xp2){
    __shared__ float red[256];
    int m = blockIdx.x, t = threadIdx.x;
    GDC_WAIT();
    GDC_LAUNCH();
    int tok = ids[m];
    const float2* row2 = (const float2*)(W_emb + (size_t)tok*Dm);
    float2 a = row2[t], b = row2[t+256];
    float s = a.x*a.x + a.y*a.y + b.x*b.x + b.y*b.y;
    s = blocksum256(s, red);
    float f = l2fac(sqrtf(s));
    a.x*=f; a.y*=f; b.x*=f; b.y*=f;
    float2* x2 = (float2*)(x + (size_t)m*Dm);
    x2[t] = a; x2[t+256] = b;
    xp2[cidx(m, t,     NCKD)] = packh2(a.x, a.y);
    xp2[cidx(m, t+256, NCKD)] = packh2(b.x, b.y);
}

// ---------------- fused attn-prep + delta rule ----------------
#define DCH 32
__global__ void delta_k(const float* __restrict__ qkv, const float* __restrict__ qs_l,
                        const float* __restrict__ Wbeta, const float* __restrict__ bscale,
                        int l, int is_l0, float* __restrict__ v0h,
                        uint32_t* __restrict__ op2, const float* __restrict__ fWo){
    int bh = blockIdx.x;
    int b = bh / NH, h = bh % NH;
    int t = threadIdx.x;
    int warp = t>>5, lane = t&31;
    int col = t>>1, par = t&1;

    GDC_WAIT();
    GDC_LAUNCH();

    float wb0 = Wbeta[l*DHd + lane], wb1 = Wbeta[l*DHd + lane + 32];
    float wfac = l2fac(sqrtf(warpsum(wb0*wb0 + wb1*wb1))) * (bscale[l]*0.1f);
    float wbn0 = wb0*wfac, wbn1 = wb1*wfac;
    float qsc0 = qs_l[h*DHd + lane]*1024.0f, qsc1 = qs_l[h*DHd + lane + 32]*1024.0f;

    float St[32];
    #pragma unroll
    for(int i=0;i<32;i++) St[i] = 0.0f;

    __shared__ float ks[DCH*DHd];
    __shared__ float qs[DCH*DHd];
    __shared__ float vs[DCH*DHd];
    __shared__ float bs[DCH];

    float fo = fWo[h*DHd + col];

    for(int c0=0;c0<SEQn;c0+=DCH){
        __syncthreads();
        #pragma unroll
        for(int j=0;j<8;j++){
            int i = warp + 4*j;
            int m = b*SEQn + c0 + i;
            size_t src = (size_t)m*NQKV + h*DHd;
            float q0=qkv[src+lane],       q1=qkv[src+lane+32];
            float k0=qkv[src+Dm+lane],    k1=qkv[src+Dm+lane+32];
            float v0=qkv[src+2*Dm+lane],  v1=qkv[src+2*Dm+lane+32];
            float fq = l2fac(sqrtf(warpsum(q0*q0 + q1*q1)));
            float fk = l2fac(sqrtf(warpsum(k0*k0 + k1*k1)));
            float kn0 = k0*fk, kn1 = k1*fk;
            float bd = warpsum(kn0*wbn0 + kn1*wbn1);
            size_t vdst = ((size_t)bh*SEQn + c0 + i)*DHd;
            float vv0, vv1;
            if(is_l0){ vv0=v0; vv1=v1; v0h[vdst+lane]=v0; v0h[vdst+lane+32]=v1; }
            else     { vv0=0.5f*(v0 + v0h[vdst+lane]); vv1=0.5f*(v1 + v0h[vdst+lane+32]); }
            qs[i*DHd+lane] = q0*fq*qsc0;  qs[i*DHd+lane+32] = q1*fq*qsc1;
            ks[i*DHd+lane] = kn0;         ks[i*DHd+lane+32] = kn1;
            vs[i*DHd+lane] = vv0;         vs[i*DHd+lane+32] = vv1;
            if(lane==0) bs[i] = 1.0f/(1.0f + __expf(-bd));
        }
        __syncthreads();
        for(int tt=0;tt<DCH;tt++){
            const float* kt = &ks[tt*DHd];
            const float* qt = &qs[tt*DHd];
            float p0=0,p1=0,p2=0,p3=0;
            #pragma unroll
            for(int j=0;j<32;j+=4){
                p0 += kt[2*j+par]*St[j];
                p1 += kt[2*(j+1)+par]*St[j+1];
                p2 += kt[2*(j+2)+par]*St[j+2];
                p3 += kt[2*(j+3)+par]*St[j+3];
            }
            float kS = (p0+p1)+(p2+p3);
            kS += __shfl_xor_sync(0xffffffffu, kS, 1);
            float dlt = bs[tt]*(vs[tt*DHd + col] - kS);
            float o0=0,o1=0,o2=0,o3=0;
            #pragma unroll
            for(int j=0;j<32;j+=4){
                St[j]   += kt[2*j+par]*dlt;     o0 += qt[2*j+par]*St[j];
                St[j+1] += kt[2*(j+1)+par]*dlt; o1 += qt[2*(j+1)+par]*St[j+1];
                St[j+2] += kt[2*(j+2)+par]*dlt; o2 += qt[2*(j+2)+par]*St[j+2];
                St[j+3] += kt[2*(j+3)+par]*dlt; o3 += qt[2*(j+3)+par]*St[j+3];
            }
            float o = (o0+o1)+(o2+o3);
            o += __shfl_xor_sync(0xffffffffu, o, 1);
            o *= fo;
            float oN = __shfl_down_sync(0xffffffffu, o, 2);
            if((t & 3) == 0){
                int m = b*SEQn + c0 + tt;
                op2[cidx(m, h*32 + (col>>1), NCKD)] = packh2(o, oN);
            }
        }
    }
}

// ---------------- residual ----------------
__global__ void resid_k(float* __restrict__ x, const float* __restrict__ o,
                        const float* __restrict__ alpha, uint32_t* __restrict__ xp2){
    __shared__ float red[256];
    int m = blockIdx.x, t = threadIdx.x;
    GDC_WAIT();
    GDC_LAUNCH();
    const float2* o2 = (const float2*)(o + (size_t)m*Dm);
    float2 oa = o2[t], ob = o2[t+256];
    float s = oa.x*oa.x + oa.y*oa.y + ob.x*ob.x + ob.y*ob.y;
    s = blocksum256(s, red);
    float fh = l2fac(sqrtf(s));
    float2* x2 = (float2*)(x + (size_t)m*Dm);
    float2 xa = x2[t], xb = x2[t+256];
    const float2* al2 = (const float2*)alpha;
    float2 aa = al2[t], ab = al2[t+256];
    float ya0 = xa.x + aa.x*8.0f*(oa.x*fh - xa.x);
    float ya1 = xa.y + aa.y*8.0f*(oa.y*fh - xa.y);
    float yb0 = xb.x + ab.x*8.0f*(ob.x*fh - xb.x);
    float yb1 = xb.y + ab.y*8.0f*(ob.y*fh - xb.y);
    float s2 = ya0*ya0 + ya1*ya1 + yb0*yb0 + yb1*yb1;
    s2 = blocksum256(s2, red);
    float f2 = l2fac(sqrtf(s2));
    ya0*=f2; ya1*=f2; yb0*=f2; yb1*=f2;
    x2[t]     = make_float2(ya0, ya1);
    x2[t+256] = make_float2(yb0, yb1);
    xp2[cidx(m, t,     NCKD)] = packh2(ya0, ya1);
    xp2[cidx(m, t+256, NCKD)] = packh2(yb0, yb1);
}

// ---------------- host ----------------
struct GraphAux {
    cudaStream_t s1;
    cudaEvent_t evRoot, evCn1, evO, evQ, evHg, evFo, evLog;
    GraphAux(){
        cudaStreamCreateWithFlags(&s1, cudaStreamNonBlocking);
        cudaEventCreateWithFlags(&evRoot, cudaEventDisableTiming);
        cudaEventCreateWithFlags(&evCn1,  cudaEventDisableTiming);
        cudaEventCreateWithFlags(&evO,    cudaEventDisableTiming);
        cudaEventCreateWithFlags(&evQ,    cudaEventDisableTiming);
        cudaEventCreateWithFlags(&evHg,   cudaEventDisableTiming);
        cudaEventCreateWithFlags(&evFo,   cudaEventDisableTiming);
        cudaEventCreateWithFlags(&evLog,  cudaEventDisableTiming);
    }
};
static GraphAux g_aux;

template<typename T> static void* symaddr(T& s){
    void* p = nullptr; cudaGetSymbolAddress(&p, s); return p;
}

// PDL launch on stream 0
template<typename F, typename... Args>
static void pdl(F fn, dim3 gr, dim3 bl, size_t sh, Args... args){
    cudaLaunchConfig_t cfg = {};
    cfg.gridDim = gr; cfg.blockDim = bl; cfg.dynamicSmemBytes = sh; cfg.stream = 0;
    cudaLaunchAttribute at{};
    at.id = cudaLaunchAttributeProgrammaticStreamSerialization;
    at.val.programmaticStreamSerializationAllowed = 1;
    cfg.attrs = &at; cfg.numAttrs = 1;
    cudaLaunchKernelEx(&cfg, fn, args...);
}

extern "C" void kernel_launch(void* const* d_in, const int* in_sizes, int n_in,
                              void* d_out, int out_size){
    (void)in_sizes; (void)n_in; (void)out_size;
    const int*   ids        = (const int*)  d_in[0];
    const float* W_emb      = (const float*)d_in[2];
    const float* Wq         = (const float*)d_in[3];
    const float* Wk         = (const float*)d_in[4];
    const float* Wv         = (const float*)d_in[5];
    const float* Wbeta      = (const float*)d_in[6];
    const float* Wo         = (const float*)d_in[7];
    const float* Wffh       = (const float*)d_in[8];
    const float* Wffg       = (const float*)d_in[9];
    const float* Wffo       = (const float*)d_in[10];
    const float* qk_scale   = (const float*)d_in[11];
    const float* beta_scale = (const float*)d_in[12];
    const float* attn_alpha = (const float*)d_in[13];
    const float* ff_alpha   = (const float*)d_in[14];
    const float* ffh_scale  = (const float*)d_in[15];
    const float* ffg_scale  = (const float*)d_in[16];
    const float* W_logits   = (const float*)d_in[17];
    const float* logit_scale= (const float*)d_in[18];
    float* out = (float*)d_out;

    float* x     = (float*)symaddr(g_x);
    float* qkv   = (float*)symaddr(g_qkv);
    float* obuf  = (float*)symaddr(g_obuf);
    float* v0h   = (float*)symaddr(g_v0h);
    float* fo    = (float*)symaddr(g_fo);
    float* fffo  = (float*)symaddr(g_fffo);
    float* part  = (float*)symaddr(g_part);
    uint32_t* xp2   = (uint32_t*)symaddr(g_xp2);
    uint32_t* op2   = (uint32_t*)symaddr(g_op2);
    uint32_t* zp2   = (uint32_t*)symaddr(g_zp2);
    uint32_t* wqkv2 = (uint32_t*)symaddr(g_wqkv2);
    uint32_t* wo2   = (uint32_t*)symaddr(g_wo2);
    uint32_t* whg2  = (uint32_t*)symaddr(g_whg2);
    uint32_t* wfo2  = (uint32_t*)symaddr(g_wfo2);
    uint32_t* wl2   = (uint32_t*)symaddr(g_wl2);

    cudaFuncSetAttribute(gemm_mma_k<128,128,64,32,3,0>, cudaFuncAttributeMaxDynamicSharedMemorySize, 99328);
    cudaFuncSetAttribute(gemm_hg_k<128,128,64,32,3>,    cudaFuncAttributeMaxDynamicSharedMemorySize, 99328);
    cudaFuncSetAttribute(gemm_mma_k<64,64,32,16,6,0>,   cudaFuncAttributeMaxDynamicSharedMemorySize, 99328);

    cudaStream_t s1 = g_aux.s1;

    cudaEventRecord(g_aux.evRoot, 0);
    cudaStreamWaitEvent(s1, g_aux.evRoot, 0);

    // side stream: deferred packing, earliest-consumer order
    colnorm_part_k<<<dim3(Dm/256, NL, 8), 256, 0, s1>>>(Wo, part, Dm, Dm);
    colnorm_fin_k<<<dim3(Dm/256, NL), 256, 0, s1>>>(part, fo, Dm);
    cudaEventRecord(g_aux.evCn1, s1);
    wpack_o_k<<<NL*Dm, 256, 0, s1>>>(Wo, wo2);
    cudaEventRecord(g_aux.evO, s1);
    wpack_qkv_k<<<3*NQKV, 256, 0, s1>>>(Wq, Wk, Wv, 1, wqkv2);
    cudaEventRecord(g_aux.evQ, s1);
    wpack_hg_k<<<NL*NHG, 256, 0, s1>>>(Wffh, Wffg, ffh_scale, ffg_scale, whg2);
    cudaEventRecord(g_aux.evHg, s1);
    colnorm_part_k<<<dim3((DFFn+255)/256, NL, 8), 256, 0, s1>>>(Wffo, part, Dm, DFFn);
    colnorm_fin_k<<<dim3((DFFn+255)/256, NL), 256, 0, s1>>>(part, fffo, DFFn);
    wpack_fo_k<<<NL*Dm, 256, 0, s1>>>(Wffo, fffo, wfo2);
    cudaEventRecord(g_aux.evFo, s1);
    wpack_log_k<<<NV, 256, 0, s1>>>(W_logits, logit_scale, wl2);
    cudaEventRecord(g_aux.evLog, s1);

    // main stream
    wpack_qkv_k<<<NQKV, 256>>>(Wq, Wk, Wv, 0, wqkv2);
    pdl(embed_k, dim3(MT), dim3(256), 0, ids, W_emb, x, xp2);

    for(int l=0;l<NL;l++){
        if(l==1) cudaStreamWaitEvent(0, g_aux.evQ, 0);
        pdl(gemm_mma_k<128,128,64,32,3,0>, dim3(8, NQKV/128), dim3(256), 99328,
            (const uint32_t*)xp2, (const uint32_t*)(wqkv2 + (size_t)l*NQKV*UD),
            (void*)qkv, NQKV, Dm);
        if(l==0) cudaStreamWaitEvent(0, g_aux.evCn1, 0);
        pdl(delta_k, dim3(NB*NH), dim3(128), 0,
            (const float*)qkv, (const float*)(qk_scale + l*Dm), Wbeta, beta_scale,
            l, (l==0)?1:0, v0h, op2, (const float*)(fo + l*Dm));
        if(l==0) cudaStreamWaitEvent(0, g_aux.evO, 0);
        pdl(gemm_mma_k<64,64,32,16,6,0>, dim3(16, 16), dim3(256), 99328,
            (const uint32_t*)op2, (const uint32_t*)(wo2 + (size_t)l*Dm*UD),
            (void*)obuf, Dm, Dm);
        pdl(resid_k, dim3(MT), dim3(256), 0,
            x, (const float*)obuf, (const float*)(attn_alpha + l*Dm), xp2);
        if(l==0) cudaStreamWaitEvent(0, g_aux.evHg, 0);
        pdl(gemm_hg_k<128,128,64,32,3>, dim3(8, NHG/128), dim3(256), 99328,
            (const uint32_t*)xp2, (const uint32_t*)(whg2 + (size_t)l*NHG*UD),
            zp2, NCKF, Dm);
        if(l==0) cudaStreamWaitEvent(0, g_aux.evFo, 0);
        pdl(gemm_mma_k<64,64,32,16,6,0>, dim3(16, 16), dim3(256), 99328,
            (const uint32_t*)zp2, (const uint32_t*)(wfo2 + (size_t)l*Dm*UF),
            (void*)obuf, Dm, DFFP);
        pdl(resid_k, dim3(MT), dim3(256), 0,
            x, (const float*)obuf, (const float*)(ff_alpha + l*Dm), xp2);
    }
    cudaStreamWaitEvent(0, g_aux.evLog, 0);
    pdl(gemm_mma_k<128,128,64,32,3,0>, dim3(8, NV/128), dim3(256), 99328,
        (const uint32_t*)xp2, (const uint32_t*)wl2, (void*)out, NV, Dm);
}

// round 14
// speedup vs baseline: 1.1767x; 1.1767x over previous
#include <cuda_runtime.h>
#include <cuda_bf16.h>
#include <cuda_fp16.h>
#include <math.h>
#include <stdint.h>

#define Dm    1024
#define SEQn  512
#define NB    2
#define NH    16
#define DHd   64
#define DFFn  2730
#define DFFP  2816
#define NV    32000
#define NL    4
#define MT    1024
#define NQKV  3072
#define NHG   5632
#define UD    512
#define UF    1408
#define NCKD  16
#define NCKF  44

// ---------------- fp32 scratch ----------------
__device__ float g_x[MT*Dm];
__device__ float g_qkv[MT*NQKV];
__device__ float g_obuf[MT*Dm];
__device__ float g_v0h[NB*NH*SEQn*DHd];
__device__ float g_fo[NL*Dm];
__device__ float g_fffo[NL*DFFn];
__device__ float g_part[8*NL*DFFP];

// ---------------- packed fp16 buffers, chunked pre-swizzled layout ----------------
__device__ uint32_t g_xp2 [MT*UD];
__device__ uint32_t g_op2 [MT*UD];
__device__ uint32_t g_zp2 [MT*UF];
__device__ uint32_t g_wqkv2[(size_t)NL*NQKV*UD];
__device__ uint32_t g_wo2  [(size_t)NL*Dm*UD];
__device__ uint32_t g_whg2 [(size_t)NL*NHG*UD];
__device__ uint32_t g_wfo2 [(size_t)NL*Dm*UF];
__device__ uint32_t g_wl2  [(size_t)NV*UD];

static __device__ __forceinline__ size_t cidx(int gr, int j, int ncK){
    return ((size_t)(gr>>7)*ncK + (j>>5))*4096 + (size_t)(gr&127)*32
         + ((((j>>2)&7) ^ (gr&7))<<2) + (j&3);
}

// ---------------- scalar helpers ----------------
static __device__ __forceinline__ float l2fac(float n){
    float tgt = fminf(fmaxf(n, 1.0f - 1e-5f), 1.0f + 1e-5f);
    return 1.0f / fmaxf(n / tgt, 1e-10f);
}
static __device__ __forceinline__ float warpsum(float v){
    #pragma unroll
    for(int o=16;o>0;o>>=1) v += __shfl_xor_sync(0xffffffffu, v, o);
    return v;
}
static __device__ __forceinline__ float blocksum256(float v, float* red){
    red[threadIdx.x] = v; __syncthreads();
    for(int o=128;o>0;o>>=1){
        if(threadIdx.x < o) red[threadIdx.x] += red[threadIdx.x+o];
        __syncthreads();
    }
    float r = red[0]; __syncthreads();
    return r;
}
static __device__ __forceinline__ uint32_t packh2(float x0, float x1){
    return (uint32_t)__half_as_ushort(__float2half_rn(x0))
         | ((uint32_t)__half_as_ushort(__float2half_rn(x1))<<16);
}

// ---------------- bulk-copy / mbarrier / ldmatrix / mma primitives ----------------
static __device__ __forceinline__ void mbar_init(uint32_t a, uint32_t c){
    asm volatile("mbarrier.init.shared.b64 [%0], %1;" :: "r"(a), "r"(c) : "memory");
}
static __device__ __forceinline__ void mbar_expect(uint32_t a, uint32_t bytes){
    asm volatile("mbarrier.arrive.expect_tx.shared.b64 _, [%0], %1;"
                 :: "r"(a), "r"(bytes) : "memory");
}
static __device__ __forceinline__ void mbar_wait(uint32_t a, uint32_t ph){
    asm volatile("{\n\t.reg .pred P;\n\t"
        "WL_%=:\n\t"
        "mbarrier.try_wait.parity.shared.b64 P, [%0], %1;\n\t"
        "@P bra.uni WD_%=;\n\t"
        "bra.uni WL_%=;\n\t"
        "WD_%=:\n\t}"
        :: "r"(a), "r"(ph) : "memory");
}
static __device__ __forceinline__ void bulkcp(uint32_t dst, const void* src, uint32_t bytes,
                                              uint32_t mbar){
    asm volatile("cp.async.bulk.shared::cluster.global.mbarrier::complete_tx::bytes "
                 "[%0], [%1], %2, [%3];"
                 :: "r"(dst), "l"(src), "r"(bytes), "r"(mbar) : "memory");
}
static __device__ __forceinline__ void ldsm4(uint32_t* r, uint32_t a){
    asm volatile("ldmatrix.sync.aligned.m8n8.x4.shared.b16 {%0,%1,%2,%3}, [%4];"
        : "=r"(r[0]),"=r"(r[1]),"=r"(r[2]),"=r"(r[3]) : "r"(a));
}
static __device__ __forceinline__ void mma_f16(float* c,
        uint32_t a0, uint32_t a1, uint32_t a2, uint32_t a3, uint32_t b0, uint32_t b1){
    asm volatile("mma.sync.aligned.m16n8k16.row.col.f32.f16.f16.f32 "
                 "{%0,%1,%2,%3},{%4,%5,%6,%7},{%8,%9},{%0,%1,%2,%3};"
                 : "+f"(c[0]), "+f"(c[1]), "+f"(c[2]), "+f"(c[3])
                 : "r"(a0), "r"(a1), "r"(a2), "r"(a3), "r"(b0), "r"(b1));
}

// ---------------- bulk-copy mma GEMM: C[M,N] = A @ B^T (fp32 out) ----------------
template<int BM,int BN,int WM,int WN,int S,int EPI>
__global__ void __launch_bounds__(256, 2)
gemm_mma_k(const uint32_t* __restrict__ Au, const uint32_t* __restrict__ Bu,
           void* __restrict__ Cv, int ldc, int Ks){
    constexpr int ABYTES = BM*128, BBYTES = BN*128, STAGE = ABYTES+BBYTES;
    constexpr int WNW = BN/WN;
    constexpr int MI = WM/16, NJ = WN/8, NJ2 = NJ/2;

    extern __shared__ char sm[];
    uint32_t smBase = (uint32_t)__cvta_generic_to_shared(sm);
    uint32_t mb = smBase;
    uint32_t tiles = smBase + 1024;

    const int tid = threadIdx.x, warp = tid>>5, lane = tid&31;
    const int wm = warp / WNW, wn = warp % WNW;
    const int i8 = lane&7, sub = lane>>3;
    const int g = lane>>2, t4 = lane&3;
    const int rowBase = blockIdx.x*BM, colBase = blockIdx.y*BN;
    const int NC = Ks>>6;

    const char* AbBase = (const char*)Au + ((size_t)(rowBase>>7)*NC)*16384
                       + (size_t)((rowBase>>6)&1)*8192;
    const char* BbBase = (const char*)Bu + ((size_t)(colBase>>7)*NC)*16384
                       + (size_t)((colBase>>6)&1)*8192;

    if(tid==0){
        #pragma unroll
        for(int s=0;s<S;s++) mbar_init(mb + 8*s, 1);
    }
    __syncthreads();
    if(tid==0){
        #pragma unroll
        for(int s=0;s<S-1;s++){
            mbar_expect(mb + 8*s, STAGE);
            bulkcp(tiles + s*STAGE,          AbBase + (size_t)s*16384, ABYTES, mb + 8*s);
            bulkcp(tiles + s*STAGE + ABYTES, BbBase + (size_t)s*16384, BBYTES, mb + 8*s);
        }
    }

    const int cA = sub>>1, cB = sub&1;
    uint32_t aRow[MI], bRow[NJ2];
    #pragma unroll
    for(int it=0;it<MI;it++)
        aRow[it] = tiles + (uint32_t)((wm*WM + it*16 + (sub&1)*8 + i8)*128);
    #pragma unroll
    for(int jp=0;jp<NJ2;jp++)
        bRow[jp] = tiles + (uint32_t)(ABYTES + (wn*WN + jp*16 + (sub>>1)*8 + i8)*128);

    float acc[MI][NJ][4];
    #pragma unroll
    for(int i=0;i<MI;i++)
        #pragma unroll
        for(int j=0;j<NJ;j++)
            #pragma unroll
            for(int e=0;e<4;e++) acc[i][j][e] = 0.0f;

    uint32_t ahB[2][MI][4], bbB[2][NJ2][4];

    for(int c=0;c<NC;c++){
        int s = c % S;
        mbar_wait(mb + 8*s, (uint32_t)((c/S)&1));
        if(tid==0 && c+S-1 < NC){
            int s2 = (c+S-1)%S;
            mbar_expect(mb + 8*s2, STAGE);
            bulkcp(tiles + s2*STAGE,          AbBase + (size_t)(c+S-1)*16384, ABYTES, mb + 8*s2);
            bulkcp(tiles + s2*STAGE + ABYTES, BbBase + (size_t)(c+S-1)*16384, BBYTES, mb + 8*s2);
        }
        const uint32_t bufOff = (uint32_t)(s*STAGE);

        #define LD_FRAG(kk, p) do{                                                   \
            _Pragma("unroll")                                                        \
            for(int it_=0;it_<MI;it_++)                                              \
                ldsm4(ahB[p][it_], aRow[it_] + bufOff + (uint32_t)((((2*(kk) + cA) ^ i8))<<4)); \
            _Pragma("unroll")                                                        \
            for(int jp_=0;jp_<NJ2;jp_++)                                             \
                ldsm4(bbB[p][jp_], bRow[jp_] + bufOff + (uint32_t)((((2*(kk) + cB) ^ i8))<<4)); \
        }while(0)

        LD_FRAG(0, 0);
        #pragma unroll
        for(int kk=0;kk<4;kk++){
            const int cur = kk&1;
            if(kk<3) LD_FRAG(kk+1, cur^1);
            #pragma unroll
            for(int it=0;it<MI;it++)
                #pragma unroll
                for(int jt=0;jt<NJ;jt++){
                    const uint32_t* bf = bbB[cur][jt>>1];
                    int o = (jt&1)*2;
                    mma_f16(acc[it][jt], ahB[cur][it][0], ahB[cur][it][1],
                            ahB[cur][it][2], ahB[cur][it][3], bf[o], bf[o+1]);
                }
        }
        #undef LD_FRAG
        __syncthreads();
    }

    float* C = (float*)Cv;
    #pragma unroll
    for(int jt=0;jt<NJ;jt++){
        int c = colBase + wn*WN + jt*8 + t4*2;
        #pragma unroll
        for(int it=0;it<MI;it++){
            int r = rowBase + wm*WM + it*16 + g;
            *(float2*)(C + (size_t)r*ldc + c)     = make_float2(acc[it][jt][0], acc[it][jt][1]);
            *(float2*)(C + (size_t)(r+8)*ldc + c) = make_float2(acc[it][jt][2], acc[it][jt][3]);
        }
    }
}

// hg GEMM: (h,g) col pairs -> packed fp16 silu(g)*h into chunked C
template<int BM,int BN,int WM,int WN,int S>
__global__ void __launch_bounds__(256, 2)
gemm_hg_k(const uint32_t* __restrict__ Au, const uint32_t* __restrict__ Bu,
          uint32_t* __restrict__ Cv, int ncK, int Ks){
    constexpr int ABYTES = BM*128, BBYTES = BN*128, STAGE = ABYTES+BBYTES;
    constexpr int WNW = BN/WN;
    constexpr int MI = WM/16, NJ = WN/8, NJ2 = NJ/2;

    extern __shared__ char sm[];
    uint32_t smBase = (uint32_t)__cvta_generic_to_shared(sm);
    uint32_t mb = smBase;
    uint32_t tiles = smBase + 1024;

    const int tid = threadIdx.x, warp = tid>>5, lane = tid&31;
    const int wm = warp / WNW, wn = warp % WNW;
    const int i8 = lane&7, sub = lane>>3;
    const int g = lane>>2, t4 = lane&3;
    const int rowBase = blockIdx.x*BM, colBase = blockIdx.y*BN;
    const int NC = Ks>>6;

    const char* AbBase = (const char*)Au + ((size_t)(rowBase>>7)*NC)*16384
                       + (size_t)((rowBase>>6)&1)*8192;
    const char* BbBase = (const char*)Bu + ((size_t)(colBase>>7)*NC)*16384
                       + (size_t)((colBase>>6)&1)*8192;

    if(tid==0){
        #pragma unroll
        for(int s=0;s<S;s++) mbar_init(mb + 8*s, 1);
    }
    __syncthreads();
    if(tid==0){
        #pragma unroll
        for(int s=0;s<S-1;s++){
            mbar_expect(mb + 8*s, STAGE);
            bulkcp(tiles + s*STAGE,          AbBase + (size_t)s*16384, ABYTES, mb + 8*s);
            bulkcp(tiles + s*STAGE + ABYTES, BbBase + (size_t)s*16384, BBYTES, mb + 8*s);
        }
    }

    const int cA = sub>>1, cB = sub&1;
    uint32_t aRow[MI], bRow[NJ2];
    #pragma unroll
    for(int it=0;it<MI;it++)
        aRow[it] = tiles + (uint32_t)((wm*WM + it*16 + (sub&1)*8 + i8)*128);
    #pragma unroll
    for(int jp=0;jp<NJ2;jp++)
        bRow[jp] = tiles + (uint32_t)(ABYTES + (wn*WN + jp*16 + (sub>>1)*8 + i8)*128);

    float acc[MI][NJ][4];
    #pragma unroll
    for(int i=0;i<MI;i++)
        #pragma unroll
        for(int j=0;j<NJ;j++)
            #pragma unroll
            for(int e=0;e<4;e++) acc[i][j][e] = 0.0f;

    uint32_t ahB[2][MI][4], bbB[2][NJ2][4];

    for(int c=0;c<NC;c++){
        int s = c % S;
        mbar_wait(mb + 8*s, (uint32_t)((c/S)&1));
        if(tid==0 && c+S-1 < NC){
            int s2 = (c+S-1)%S;
            mbar_expect(mb + 8*s2, STAGE);
            bulkcp(tiles + s2*STAGE,          AbBase + (size_t)(c+S-1)*16384, ABYTES, mb + 8*s2);
            bulkcp(tiles + s2*STAGE + ABYTES, BbBase + (size_t)(c+S-1)*16384, BBYTES, mb + 8*s2);
        }
        const uint32_t bufOff = (uint32_t)(s*STAGE);

        #define LD_FRAG(kk, p) do{                                                   \
            _Pragma("unroll")                                                        \
            for(int it_=0;it_<MI;it_++)                                              \
                ldsm4(ahB[p][it_], aRow[it_] + bufOff + (uint32_t)((((2*(kk) + cA) ^ i8))<<4)); \
            _Pragma("unroll")                                                        \
            for(int jp_=0;jp_<NJ2;jp_++)                                             \
                ldsm4(bbB[p][jp_], bRow[jp_] + bufOff + (uint32_t)((((2*(kk) + cB) ^ i8))<<4)); \
        }while(0)

        LD_FRAG(0, 0);
        #pragma unroll
        for(int kk=0;kk<4;kk++){
            const int cur = kk&1;
            if(kk<3) LD_FRAG(kk+1, cur^1);
            #pragma unroll
            for(int it=0;it<MI;it++)
                #pragma unroll
                for(int jt=0;jt<NJ;jt++){
                    const uint32_t* bf = bbB[cur][jt>>1];
                    int o = (jt&1)*2;
                    mma_f16(acc[it][jt], ahB[cur][it][0], ahB[cur][it][1],
                            ahB[cur][it][2], ahB[cur][it][3], bf[o], bf[o+1]);
                }
        }
        #undef LD_FRAG
        __syncthreads();
    }

    #pragma unroll
    for(int jt=0;jt<NJ;jt++){
        int i0 = ((colBase + wn*WN + jt*8)>>1) + t4;
        #pragma unroll
        for(int it=0;it<MI;it++){
            int r = rowBase + wm*WM + it*16 + g;
            float h0 = acc[it][jt][0], g0 = acc[it][jt][1];
            float h1 = acc[it][jt][2], g1 = acc[it][jt][3];
            float z0 = g0/(1.0f + __expf(-g0))*h0;
            float z1 = g1/(1.0f + __expf(-g1))*h1;
            float z0n = __shfl_xor_sync(0xffffffffu, z0, 1);
            float z1n = __shfl_xor_sync(0xffffffffu, z1, 1);
            if((t4 & 1) == 0){
                int j = i0>>1;
                Cv[cidx(r,   j, ncK)] = packh2(z0, z0n);
                Cv[cidx(r+8, j, ncK)] = packh2(z1, z1n);
            }
        }
    }
}

// ---------------- split column norms: 8-way row partials + finalize ----------------
__global__ void colnorm_part_k(const float* __restrict__ W, float* __restrict__ part,
                               int R, int C){
    int l = blockIdx.y;
    int c = blockIdx.x*256 + threadIdx.x;
    int sp = blockIdx.z;
    if(c >= C) return;
    const float* Wl = W + (size_t)l*R*C;
    int r0 = sp*(R>>3), r1 = r0 + (R>>3);
    float s = 0.0f;
    for(int r=r0;r<r1;r++){ float w = Wl[(size_t)r*C + c]; s += w*w; }
    part[((size_t)sp*NL + l)*DFFP + c] = s;
}
__global__ void colnorm_fin_k(const float* __restrict__ part, float* __restrict__ f, int C){
    int l = blockIdx.y;
    int c = blockIdx.x*256 + threadIdx.x;
    if(c >= C) return;
    float s = 0.0f;
    #pragma unroll
    for(int sp=0;sp<8;sp++) s += part[((size_t)sp*NL + l)*DFFP + c];
    f[(size_t)l*C + c] = l2fac(sqrtf(s));
}

// ---------------- fused norm + pack kernels ----------------
__global__ void wpack_qkv_k(const float* __restrict__ Wq, const float* __restrict__ Wk,
                            const float* __restrict__ Wv, int lbase,
                            uint32_t* __restrict__ dst){
    __shared__ float red[256];
    int rr = blockIdx.x + lbase*NQKV;
    int l = rr / NQKV, r = rr % NQKV;
    int which = r >> 10, rl = r & 1023;
    const float* W = (which==0) ? Wq : (which==1) ? Wk : Wv;
    const float4* sp = (const float4*)(W + ((size_t)l*Dm + rl)*Dm);
    float4 v = sp[threadIdx.x];
    float s = v.x*v.x + v.y*v.y + v.z*v.z + v.w*v.w;
    s = blocksum256(s, red);
    float f = l2fac(sqrtf(s));
    dst[cidx(rr, 2*threadIdx.x,   NCKD)] = packh2(v.x*f, v.y*f);
    dst[cidx(rr, 2*threadIdx.x+1, NCKD)] = packh2(v.z*f, v.w*f);
}
__global__ void wpack_o_k(const float* __restrict__ Wo, uint32_t* __restrict__ dst){
    int rr = blockIdx.x;
    const float4* sp = (const float4*)(Wo + (size_t)rr*Dm);
    float4 v = sp[threadIdx.x];
    dst[cidx(rr, 2*threadIdx.x,   NCKD)] = packh2(v.x, v.y);
    dst[cidx(rr, 2*threadIdx.x+1, NCKD)] = packh2(v.z, v.w);
}
__global__ void wpack_hg_k(const float* __restrict__ Wffh, const float* __restrict__ Wffg,
                           const float* __restrict__ hsc, const float* __restrict__ gsc,
                           uint32_t* __restrict__ dst){
    __shared__ float red[256];
    int rr = blockIdx.x;
    int l = rr / NHG, r = rr % NHG;
    int p = r >> 1, isG = r & 1;
    if(p >= DFFn){
        dst[cidx(rr, 2*threadIdx.x,   NCKD)] = 0u;
        dst[cidx(rr, 2*threadIdx.x+1, NCKD)] = 0u;
        return;
    }
    size_t sr = (size_t)l*DFFn + p;
    const float* W = isG ? (Wffg + sr*Dm) : (Wffh + sr*Dm);
    float sc = isG ? gsc[sr]*32.0f : hsc[sr];
    float4 v = ((const float4*)W)[threadIdx.x];
    float s = v.x*v.x + v.y*v.y + v.z*v.z + v.w*v.w;
    s = blocksum256(s, red);
    float f = l2fac(sqrtf(s))*sc;
    dst[cidx(rr, 2*threadIdx.x,   NCKD)] = packh2(v.x*f, v.y*f);
    dst[cidx(rr, 2*threadIdx.x+1, NCKD)] = packh2(v.z*f, v.w*f);
}
__global__ void wpack_fo_k(const float* __restrict__ Wffo, const float* __restrict__ fffo,
                           uint32_t* __restrict__ dst){
    int rr = blockIdx.x;
    int l = rr / Dm, rl = rr % Dm;
    const float2* sp = (const float2*)(Wffo + ((size_t)l*Dm + rl)*DFFn);
    const float* ks = fffo + (size_t)l*DFFn;
    for(int j=threadIdx.x;j<UF;j+=256){
        float x0=0.0f, x1=0.0f;
        if(2*j < DFFn){ float2 vv = sp[j]; x0 = vv.x*ks[2*j]; x1 = vv.y*ks[2*j+1]; }
        dst[cidx(rr, j, NCKF)] = packh2(x0, x1);
    }
}
__global__ void wpack_log_k(const float* __restrict__ Wl, const float* __restrict__ lsc,
                            uint32_t* __restrict__ dst){
    __shared__ float red[256];
    int r = blockIdx.x;
    const float4* sp = (const float4*)(Wl + (size_t)r*Dm);
    float4 v = sp[threadIdx.x];
    float s = v.x*v.x + v.y*v.y + v.z*v.z + v.w*v.w;
    s = blocksum256(s, red);
    float f = l2fac(sqrtf(s))*lsc[r]*32.0f;
    dst[cidx(r, 2*threadIdx.x,   NCKD)] = packh2(v.x*f, v.y*f);
    dst[cidx(r, 2*threadIdx.x+1, NCKD)] = packh2(v.z*f, v.w*f);
}

// ---------------- embedding ----------------
__global__ void embed_k(const int* __restrict__ ids, const float* __restrict__ W_emb,
                        float* __restrict__ x, uint32_t* __restrict__ xp2){
    __shared__ float red[256];
    int m = blockIdx.x, t = threadIdx.x;
    int tok = ids[m];
    const float2* row2 = (const float2*)(W_emb + (size_t)tok*Dm);
    float2 a = row2[t], b = row2[t+256];
    float s = a.x*a.x + a.y*a.y + b.x*b.x + b.y*b.y;
    s = blocksum256(s, red);
    float f = l2fac(sqrtf(s));
    a.x*=f; a.y*=f; b.x*=f; b.y*=f;
    float2* x2 = (float2*)(x + (size_t)m*Dm);
    x2[t] = a; x2[t+256] = b;
    xp2[cidx(m, t,     NCKD)] = packh2(a.x, a.y);
    xp2[cidx(m, t+256, NCKD)] = packh2(b.x, b.y);
}

// ---------------- fused attn-prep + delta rule (256 threads, 4-way k-split) ----------------
#define DCH 32
__global__ void __launch_bounds__(256)
delta_k(const float* __restrict__ qkv, const float* __restrict__ qs_l,
        const float* __restrict__ Wbeta, const float* __restrict__ bscale,
        int l, int is_l0, float* __restrict__ v0h,
        uint32_t* __restrict__ op2, const float* __restrict__ fWo){
    int bh = blockIdx.x;
    int b = bh / NH, h = bh % NH;
    int t = threadIdx.x;                 // 0..255
    int warp = t>>5, lane = t&31;
    int col = t>>2, par = t&3;           // 4 threads per state column

    float wb0 = Wbeta[l*DHd + lane], wb1 = Wbeta[l*DHd + lane + 32];
    float wfac = l2fac(sqrtf(warpsum(wb0*wb0 + wb1*wb1))) * (bscale[l]*0.1f);
    float wbn0 = wb0*wfac, wbn1 = wb1*wfac;
    float qsc0 = qs_l[h*DHd + lane]*1024.0f, qsc1 = qs_l[h*DHd + lane + 32]*1024.0f;

    float St[16];                        // state rows 4j+par, column col
    #pragma unroll
    for(int i=0;i<16;i++) St[i] = 0.0f;

    __shared__ float ks[DCH*DHd];
    __shared__ float qs[DCH*DHd];
    __shared__ float vs[DCH*DHd];
    __shared__ float bs[DCH];

    float fo = fWo[h*DHd + col];

    for(int c0=0;c0<SEQn;c0+=DCH){
        __syncthreads();
        // staging: 8 warps x 4 tokens
        #pragma unroll
        for(int j=0;j<4;j++){
            int i = warp + 8*j;
            int m = b*SEQn + c0 + i;
            size_t src = (size_t)m*NQKV + h*DHd;
            float q0=qkv[src+lane],       q1=qkv[src+lane+32];
            float k0=qkv[src+Dm+lane],    k1=qkv[src+Dm+lane+32];
            float v0=qkv[src+2*Dm+lane],  v1=qkv[src+2*Dm+lane+32];
            float fq = l2fac(sqrtf(warpsum(q0*q0 + q1*q1)));
            float fk = l2fac(sqrtf(warpsum(k0*k0 + k1*k1)));
            float kn0 = k0*fk, kn1 = k1*fk;
            float bd = warpsum(kn0*wbn0 + kn1*wbn1);
            size_t vdst = ((size_t)bh*SEQn + c0 + i)*DHd;
            float vv0, vv1;
            if(is_l0){ vv0=v0; vv1=v1; v0h[vdst+lane]=v0; v0h[vdst+lane+32]=v1; }
            else     { vv0=0.5f*(v0 + v0h[vdst+lane]); vv1=0.5f*(v1 + v0h[vdst+lane+32]); }
            qs[i*DHd+lane] = q0*fq*qsc0;  qs[i*DHd+lane+32] = q1*fq*qsc1;
            ks[i*DHd+lane] = kn0;         ks[i*DHd+lane+32] = kn1;
            vs[i*DHd+lane] = vv0;         vs[i*DHd+lane+32] = vv1;
            if(lane==0) bs[i] = 1.0f/(1.0f + __expf(-bd));
        }
        __syncthreads();
        for(int tt=0;tt<DCH;tt++){
            const float* kt = &ks[tt*DHd];
            const float* qt = &qs[tt*DHd];
            float p0=0,p1=0,p2=0,p3=0;
            #pragma unroll
            for(int j=0;j<16;j+=4){
                p0 += kt[4*j+par]*St[j];
                p1 += kt[4*(j+1)+par]*St[j+1];
                p2 += kt[4*(j+2)+par]*St[j+2];
                p3 += kt[4*(j+3)+par]*St[j+3];
            }
            float kS = (p0+p1)+(p2+p3);
            kS += __shfl_xor_sync(0xffffffffu, kS, 1);
            kS += __shfl_xor_sync(0xffffffffu, kS, 2);
            float dlt = bs[tt]*(vs[tt*DHd + col] - kS);
            float o0=0,o1=0,o2=0,o3=0;
            #pragma unroll
            for(int j=0;j<16;j+=4){
                St[j]   += kt[4*j+par]*dlt;     o0 += qt[4*j+par]*St[j];
                St[j+1] += kt[4*(j+1)+par]*dlt; o1 += qt[4*(j+1)+par]*St[j+1];
                St[j+2] += kt[4*(j+2)+par]*dlt; o2 += qt[4*(j+2)+par]*St[j+2];
                St[j+3] += kt[4*(j+3)+par]*dlt; o3 += qt[4*(j+3)+par]*St[j+3];
            }
            float o = (o0+o1)+(o2+o3);
            o += __shfl_xor_sync(0xffffffffu, o, 1);
            o += __shfl_xor_sync(0xffffffffu, o, 2);
            o *= fo;
            float oN = __shfl_down_sync(0xffffffffu, o, 4);
            if((t & 7) == 0){
                int m = b*SEQn + c0 + tt;
                op2[cidx(m, h*32 + (col>>1), NCKD)] = packh2(o, oN);
            }
        }
    }
}

// ---------------- residual ----------------
__global__ void resid_k(float* __restrict__ x, const float* __restrict__ o,
                        const float* __restrict__ alpha, uint32_t* __restrict__ xp2){
    __shared__ float red[256];
    int m = blockIdx.x, t = threadIdx.x;
    const float2* o2 = (const float2*)(o + (size_t)m*Dm);
    float2 oa = o2[t], ob = o2[t+256];
    float s = oa.x*oa.x + oa.y*oa.y + ob.x*ob.x + ob.y*ob.y;
    s = blocksum256(s, red);
    float fh = l2fac(sqrtf(s));
    float2* x2 = (float2*)(x + (size_t)m*Dm);
    float2 xa = x2[t], xb = x2[t+256];
    const float2* al2 = (const float2*)alpha;
    float2 aa = al2[t], ab = al2[t+256];
    float ya0 = xa.x + aa.x*8.0f*(oa.x*fh - xa.x);
    float ya1 = xa.y + aa.y*8.0f*(oa.y*fh - xa.y);
    float yb0 = xb.x + ab.x*8.0f*(ob.x*fh - xb.x);
    float yb1 = xb.y + ab.y*8.0f*(ob.y*fh - xb.y);
    float s2 = ya0*ya0 + ya1*ya1 + yb0*yb0 + yb1*yb1;
    s2 = blocksum256(s2, red);
    float f2 = l2fac(sqrtf(s2));
    ya0*=f2; ya1*=f2; yb0*=f2; yb1*=f2;
    x2[t]     = make_float2(ya0, ya1);
    x2[t+256] = make_float2(yb0, yb1);
    xp2[cidx(m, t,     NCKD)] = packh2(ya0, ya1);
    xp2[cidx(m, t+256, NCKD)] = packh2(yb0, yb1);
}

// ---------------- host ----------------
struct GraphAux {
    cudaStream_t s1;
    cudaEvent_t evRoot, evCn1, evO, evQ, evHg, evFo, evLog;
    GraphAux(){
        cudaStreamCreateWithFlags(&s1, cudaStreamNonBlocking);
        cudaEventCreateWithFlags(&evRoot, cudaEventDisableTiming);
        cudaEventCreateWithFlags(&evCn1,  cudaEventDisableTiming);
        cudaEventCreateWithFlags(&evO,    cudaEventDisableTiming);
        cudaEventCreateWithFlags(&evQ,    cudaEventDisableTiming);
        cudaEventCreateWithFlags(&evHg,   cudaEventDisableTiming);
        cudaEventCreateWithFlags(&evFo,   cudaEventDisableTiming);
        cudaEventCreateWithFlags(&evLog,  cudaEventDisableTiming);
    }
};
static GraphAux g_aux;

template<typename T> static void* symaddr(T& s){
    void* p = nullptr; cudaGetSymbolAddress(&p, s); return p;
}

extern "C" void kernel_launch(void* const* d_in, const int* in_sizes, int n_in,
                              void* d_out, int out_size){
    (void)in_sizes; (void)n_in; (void)out_size;
    const int*   ids        = (const int*)  d_in[0];
    const float* W_emb      = (const float*)d_in[2];
    const float* Wq         = (const float*)d_in[3];
    const float* Wk         = (const float*)d_in[4];
    const float* Wv         = (const float*)d_in[5];
    const float* Wbeta      = (const float*)d_in[6];
    const float* Wo         = (const float*)d_in[7];
    const float* Wffh       = (const float*)d_in[8];
    const float* Wffg       = (const float*)d_in[9];
    const float* Wffo       = (const float*)d_in[10];
    const float* qk_scale   = (const float*)d_in[11];
    const float* beta_scale = (const float*)d_in[12];
    const float* attn_alpha = (const float*)d_in[13];
    const float* ff_alpha   = (const float*)d_in[14];
    const float* ffh_scale  = (const float*)d_in[15];
    const float* ffg_scale  = (const float*)d_in[16];
    const float* W_logits   = (const float*)d_in[17];
    const float* logit_scale= (const float*)d_in[18];
    float* out = (float*)d_out;

    float* x     = (float*)symaddr(g_x);
    float* qkv   = (float*)symaddr(g_qkv);
    float* obuf  = (float*)symaddr(g_obuf);
    float* v0h   = (float*)symaddr(g_v0h);
    float* fo    = (float*)symaddr(g_fo);
    float* fffo  = (float*)symaddr(g_fffo);
    float* part  = (float*)symaddr(g_part);
    uint32_t* xp2   = (uint32_t*)symaddr(g_xp2);
    uint32_t* op2   = (uint32_t*)symaddr(g_op2);
    uint32_t* zp2   = (uint32_t*)symaddr(g_zp2);
    uint32_t* wqkv2 = (uint32_t*)symaddr(g_wqkv2);
    uint32_t* wo2   = (uint32_t*)symaddr(g_wo2);
    uint32_t* whg2  = (uint32_t*)symaddr(g_whg2);
    uint32_t* wfo2  = (uint32_t*)symaddr(g_wfo2);
    uint32_t* wl2   = (uint32_t*)symaddr(g_wl2);

    cudaFuncSetAttribute(gemm_mma_k<128,128,64,32,3,0>, cudaFuncAttributeMaxDynamicSharedMemorySize, 99328);
    cudaFuncSetAttribute(gemm_hg_k<128,64,32,32,3>,     cudaFuncAttributeMaxDynamicSharedMemorySize, 74752);
    cudaFuncSetAttribute(gemm_mma_k<64,64,32,16,4,0>,   cudaFuncAttributeMaxDynamicSharedMemorySize, 66560);

    cudaStream_t s1 = g_aux.s1;

    cudaEventRecord(g_aux.evRoot, 0);
    cudaStreamWaitEvent(s1, g_aux.evRoot, 0);

    // side stream: deferred packing, earliest-consumer order
    colnorm_part_k<<<dim3(Dm/256, NL, 8), 256, 0, s1>>>(Wo, part, Dm, Dm);
    colnorm_fin_k<<<dim3(Dm/256, NL), 256, 0, s1>>>(part, fo, Dm);
    cudaEventRecord(g_aux.evCn1, s1);
    wpack_o_k<<<NL*Dm, 256, 0, s1>>>(Wo, wo2);
    cudaEventRecord(g_aux.evO, s1);
    wpack_qkv_k<<<3*NQKV, 256, 0, s1>>>(Wq, Wk, Wv, 1, wqkv2);
    cudaEventRecord(g_aux.evQ, s1);
    wpack_hg_k<<<NL*NHG, 256, 0, s1>>>(Wffh, Wffg, ffh_scale, ffg_scale, whg2);
    cudaEventRecord(g_aux.evHg, s1);
    colnorm_part_k<<<dim3((DFFn+255)/256, NL, 8), 256, 0, s1>>>(Wffo, part, Dm, DFFn);
    colnorm_fin_k<<<dim3((DFFn+255)/256, NL), 256, 0, s1>>>(part, fffo, DFFn);
    wpack_fo_k<<<NL*Dm, 256, 0, s1>>>(Wffo, fffo, wfo2);
    cudaEventRecord(g_aux.evFo, s1);
    wpack_log_k<<<NV, 256, 0, s1>>>(W_logits, logit_scale, wl2);
    cudaEventRecord(g_aux.evLog, s1);

    // main stream
    wpack_qkv_k<<<NQKV, 256>>>(Wq, Wk, Wv, 0, wqkv2);
    embed_k<<<MT, 256>>>(ids, W_emb, x, xp2);

    for(int l=0;l<NL;l++){
        if(l==1) cudaStreamWaitEvent(0, g_aux.evQ, 0);
        gemm_mma_k<128,128,64,32,3,0><<<dim3(8, NQKV/128), 256, 99328>>>(
            xp2, wqkv2 + (size_t)l*NQKV*UD, qkv, NQKV, Dm);
        if(l==0) cudaStreamWaitEvent(0, g_aux.evCn1, 0);
        delta_k<<<NB*NH, 256>>>(qkv, qk_scale + l*Dm, Wbeta, beta_scale, l,
                                (l==0)?1:0, v0h, op2, fo + l*Dm);
        if(l==0) cudaStreamWaitEvent(0, g_aux.evO, 0);
        gemm_mma_k<64,64,32,16,4,0><<<dim3(16, 16), 256, 66560>>>(
            op2, wo2 + (size_t)l*Dm*UD, obuf, Dm, Dm);
        resid_k<<<MT, 256>>>(x, obuf, attn_alpha + l*Dm, xp2);
        if(l==0) cudaStreamWaitEvent(0, g_aux.evHg, 0);
        gemm_hg_k<128,64,32,32,3><<<dim3(8, NHG/64), 256, 74752>>>(
            xp2, whg2 + (size_t)l*NHG*UD, zp2, NCKF, Dm);
        if(l==0) cudaStreamWaitEvent(0, g_aux.evFo, 0);
        gemm_mma_k<64,64,32,16,4,0><<<dim3(16, 16), 256, 66560>>>(
            zp2, wfo2 + (size_t)l*Dm*UF, obuf, Dm, DFFP);
        resid_k<<<MT, 256>>>(x, obuf, ff_alpha + l*Dm, xp2);
    }
    cudaStreamWaitEvent(0, g_aux.evLog, 0);
    gemm_mma_k<128,128,64,32,3,0><<<dim3(8, NV/128), 256, 99328>>>(
        xp2, wl2, out, NV, Dm);
}

// round 15
// speedup vs baseline: 1.1899x; 1.0112x over previous
#include <cuda_runtime.h>
#include <cuda_bf16.h>
#include <cuda_fp16.h>
#include <math.h>
#include <stdint.h>

#define Dm    1024
#define SEQn  512
#define NB    2
#define NH    16
#define DHd   64
#define DFFn  2730
#define DFFP  2816
#define NV    32000
#define NL    4
#define MT    1024
#define NQKV  3072
#define NHG   5632
#define UD    512
#define UF    1408
#define NCKD  16
#define NCKF  44

// ---------------- fp32 scratch ----------------
__device__ float g_x[MT*Dm];
__device__ float g_qkv[MT*NQKV];
__device__ float g_obuf[MT*Dm];
__device__ float g_v0h[NB*NH*SEQn*DHd];
__device__ float g_fo[NL*Dm];
__device__ float g_fffo[NL*DFFn];
__device__ float g_part[8*NL*DFFP];

// ---------------- packed fp16 buffers, chunked pre-swizzled layout ----------------
__device__ uint32_t g_xp2 [MT*UD];
__device__ uint32_t g_op2 [MT*UD];
__device__ uint32_t g_zp2 [MT*UF];
__device__ uint32_t g_wqkv2[(size_t)NL*NQKV*UD];
__device__ uint32_t g_wo2  [(size_t)NL*Dm*UD];
__device__ uint32_t g_whg2 [(size_t)NL*NHG*UD];
__device__ uint32_t g_wfo2 [(size_t)NL*Dm*UF];
__device__ uint32_t g_wl2  [(size_t)NV*UD];

static __device__ __forceinline__ size_t cidx(int gr, int j, int ncK){
    return ((size_t)(gr>>7)*ncK + (j>>5))*4096 + (size_t)(gr&127)*32
         + ((((j>>2)&7) ^ (gr&7))<<2) + (j&3);
}

// ---------------- scalar helpers ----------------
static __device__ __forceinline__ float l2fac(float n){
    float tgt = fminf(fmaxf(n, 1.0f - 1e-5f), 1.0f + 1e-5f);
    return 1.0f / fmaxf(n / tgt, 1e-10f);
}
static __device__ __forceinline__ float warpsum(float v){
    #pragma unroll
    for(int o=16;o>0;o>>=1) v += __shfl_xor_sync(0xffffffffu, v, o);
    return v;
}
static __device__ __forceinline__ float blocksum256(float v, float* red){
    red[threadIdx.x] = v; __syncthreads();
    for(int o=128;o>0;o>>=1){
        if(threadIdx.x < o) red[threadIdx.x] += red[threadIdx.x+o];
        __syncthreads();
    }
    float r = red[0]; __syncthreads();
    return r;
}
static __device__ __forceinline__ uint32_t packh2(float x0, float x1){
    return (uint32_t)__half_as_ushort(__float2half_rn(x0))
         | ((uint32_t)__half_as_ushort(__float2half_rn(x1))<<16);
}

// ---------------- bulk-copy / mbarrier / ldmatrix / mma primitives ----------------
static __device__ __forceinline__ void mbar_init(uint32_t a, uint32_t c){
    asm volatile("mbarrier.init.shared.b64 [%0], %1;" :: "r"(a), "r"(c) : "memory");
}
static __device__ __forceinline__ void mbar_expect(uint32_t a, uint32_t bytes){
    asm volatile("mbarrier.arrive.expect_tx.shared.b64 _, [%0], %1;"
                 :: "r"(a), "r"(bytes) : "memory");
}
static __device__ __forceinline__ void mbar_wait(uint32_t a, uint32_t ph){
    asm volatile("{\n\t.reg .pred P;\n\t"
        "WL_%=:\n\t"
        "mbarrier.try_wait.parity.shared.b64 P, [%0], %1;\n\t"
        "@P bra.uni WD_%=;\n\t"
        "bra.uni WL_%=;\n\t"
        "WD_%=:\n\t}"
        :: "r"(a), "r"(ph) : "memory");
}
static __device__ __forceinline__ void bulkcp(uint32_t dst, const void* src, uint32_t bytes,
                                              uint32_t mbar){
    asm volatile("cp.async.bulk.shared::cluster.global.mbarrier::complete_tx::bytes "
                 "[%0], [%1], %2, [%3];"
                 :: "r"(dst), "l"(src), "r"(bytes), "r"(mbar) : "memory");
}
static __device__ __forceinline__ void ldsm4(uint32_t* r, uint32_t a){
    asm volatile("ldmatrix.sync.aligned.m8n8.x4.shared.b16 {%0,%1,%2,%3}, [%4];"
        : "=r"(r[0]),"=r"(r[1]),"=r"(r[2]),"=r"(r[3]) : "r"(a));
}
static __device__ __forceinline__ void mma_f16(float* c,
        uint32_t a0, uint32_t a1, uint32_t a2, uint32_t a3, uint32_t b0, uint32_t b1){
    asm volatile("mma.sync.aligned.m16n8k16.row.col.f32.f16.f16.f32 "
                 "{%0,%1,%2,%3},{%4,%5,%6,%7},{%8,%9},{%0,%1,%2,%3};"
                 : "+f"(c[0]), "+f"(c[1]), "+f"(c[2]), "+f"(c[3])
                 : "r"(a0), "r"(a1), "r"(a2), "r"(a3), "r"(b0), "r"(b1));
}

// ---------------- bulk-copy mma GEMM: C[M,N] = A @ B^T (fp32 out) ----------------
template<int BM,int BN,int WM,int WN,int S,int EPI>
__global__ void __launch_bounds__(256, 2)
gemm_mma_k(const uint32_t* __restrict__ Au, const uint32_t* __restrict__ Bu,
           void* __restrict__ Cv, int ldc, int Ks){
    constexpr int ABYTES = BM*128, BBYTES = BN*128, STAGE = ABYTES+BBYTES;
    constexpr int WNW = BN/WN;
    constexpr int MI = WM/16, NJ = WN/8, NJ2 = NJ/2;

    extern __shared__ char sm[];
    uint32_t smBase = (uint32_t)__cvta_generic_to_shared(sm);
    uint32_t mb = smBase;
    uint32_t tiles = smBase + 1024;

    const int tid = threadIdx.x, warp = tid>>5, lane = tid&31;
    const int wm = warp / WNW, wn = warp % WNW;
    const int i8 = lane&7, sub = lane>>3;
    const int g = lane>>2, t4 = lane&3;
    const int rowBase = blockIdx.x*BM, colBase = blockIdx.y*BN;
    const int NC = Ks>>6;

    const char* AbBase = (const char*)Au + ((size_t)(rowBase>>7)*NC)*16384
                       + (size_t)((rowBase>>6)&1)*8192;
    const char* BbBase = (const char*)Bu + ((size_t)(colBase>>7)*NC)*16384
                       + (size_t)((colBase>>6)&1)*8192;

    if(tid==0){
        #pragma unroll
        for(int s=0;s<S;s++) mbar_init(mb + 8*s, 1);
    }
    __syncthreads();
    if(tid==0){
        #pragma unroll
        for(int s=0;s<S-1;s++){
            mbar_expect(mb + 8*s, STAGE);
            bulkcp(tiles + s*STAGE,          AbBase + (size_t)s*16384, ABYTES, mb + 8*s);
            bulkcp(tiles + s*STAGE + ABYTES, BbBase + (size_t)s*16384, BBYTES, mb + 8*s);
        }
    }

    const int cA = sub>>1, cB = sub&1;
    uint32_t aRow[MI], bRow[NJ2];
    #pragma unroll
    for(int it=0;it<MI;it++)
        aRow[it] = tiles + (uint32_t)((wm*WM + it*16 + (sub&1)*8 + i8)*128);
    #pragma unroll
    for(int jp=0;jp<NJ2;jp++)
        bRow[jp] = tiles + (uint32_t)(ABYTES + (wn*WN + jp*16 + (sub>>1)*8 + i8)*128);

    float acc[MI][NJ][4];
    #pragma unroll
    for(int i=0;i<MI;i++)
        #pragma unroll
        for(int j=0;j<NJ;j++)
            #pragma unroll
            for(int e=0;e<4;e++) acc[i][j][e] = 0.0f;

    uint32_t ahB[2][MI][4], bbB[2][NJ2][4];

    for(int c=0;c<NC;c++){
        int s = c % S;
        mbar_wait(mb + 8*s, (uint32_t)((c/S)&1));
        if(tid==0 && c+S-1 < NC){
            int s2 = (c+S-1)%S;
            mbar_expect(mb + 8*s2, STAGE);
            bulkcp(tiles + s2*STAGE,          AbBase + (size_t)(c+S-1)*16384, ABYTES, mb + 8*s2);
            bulkcp(tiles + s2*STAGE + ABYTES, BbBase + (size_t)(c+S-1)*16384, BBYTES, mb + 8*s2);
        }
        const uint32_t bufOff = (uint32_t)(s*STAGE);

        #define LD_FRAG(kk, p) do{                                                   \
            _Pragma("unroll")                                                        \
            for(int it_=0;it_<MI;it_++)                                              \
                ldsm4(ahB[p][it_], aRow[it_] + bufOff + (uint32_t)((((2*(kk) + cA) ^ i8))<<4)); \
            _Pragma("unroll")                                                        \
            for(int jp_=0;jp_<NJ2;jp_++)                                             \
                ldsm4(bbB[p][jp_], bRow[jp_] + bufOff + (uint32_t)((((2*(kk) + cB) ^ i8))<<4)); \
        }while(0)

        LD_FRAG(0, 0);
        #pragma unroll
        for(int kk=0;kk<4;kk++){
            const int cur = kk&1;
            if(kk<3) LD_FRAG(kk+1, cur^1);
            #pragma unroll
            for(int it=0;it<MI;it++)
                #pragma unroll
                for(int jt=0;jt<NJ;jt++){
                    const uint32_t* bf = bbB[cur][jt>>1];
                    int o = (jt&1)*2;
                    mma_f16(acc[it][jt], ahB[cur][it][0], ahB[cur][it][1],
                            ahB[cur][it][2], ahB[cur][it][3], bf[o], bf[o+1]);
                }
        }
        #undef LD_FRAG
        __syncthreads();
    }

    float* C = (float*)Cv;
    #pragma unroll
    for(int jt=0;jt<NJ;jt++){
        int c = colBase + wn*WN + jt*8 + t4*2;
        #pragma unroll
        for(int it=0;it<MI;it++){
            int r = rowBase + wm*WM + it*16 + g;
            *(float2*)(C + (size_t)r*ldc + c)     = make_float2(acc[it][jt][0], acc[it][jt][1]);
            *(float2*)(C + (size_t)(r+8)*ldc + c) = make_float2(acc[it][jt][2], acc[it][jt][3]);
        }
    }
}

// hg GEMM: (h,g) col pairs -> packed fp16 silu(g)*h into chunked C
template<int BM,int BN,int WM,int WN,int S>
__global__ void __launch_bounds__(256, 2)
gemm_hg_k(const uint32_t* __restrict__ Au, const uint32_t* __restrict__ Bu,
          uint32_t* __restrict__ Cv, int ncK, int Ks){
    constexpr int ABYTES = BM*128, BBYTES = BN*128, STAGE = ABYTES+BBYTES;
    constexpr int WNW = BN/WN;
    constexpr int MI = WM/16, NJ = WN/8, NJ2 = NJ/2;

    extern __shared__ char sm[];
    uint32_t smBase = (uint32_t)__cvta_generic_to_shared(sm);
    uint32_t mb = smBase;
    uint32_t tiles = smBase + 1024;

    const int tid = threadIdx.x, warp = tid>>5, lane = tid&31;
    const int wm = warp / WNW, wn = warp % WNW;
    const int i8 = lane&7, sub = lane>>3;
    const int g = lane>>2, t4 = lane&3;
    const int rowBase = blockIdx.x*BM, colBase = blockIdx.y*BN;
    const int NC = Ks>>6;

    const char* AbBase = (const char*)Au + ((size_t)(rowBase>>7)*NC)*16384
                       + (size_t)((rowBase>>6)&1)*8192;
    const char* BbBase = (const char*)Bu + ((size_t)(colBase>>7)*NC)*16384
                       + (size_t)((colBase>>6)&1)*8192;

    if(tid==0){
        #pragma unroll
        for(int s=0;s<S;s++) mbar_init(mb + 8*s, 1);
    }
    __syncthreads();
    if(tid==0){
        #pragma unroll
        for(int s=0;s<S-1;s++){
            mbar_expect(mb + 8*s, STAGE);
            bulkcp(tiles + s*STAGE,          AbBase + (size_t)s*16384, ABYTES, mb + 8*s);
            bulkcp(tiles + s*STAGE + ABYTES, BbBase + (size_t)s*16384, BBYTES, mb + 8*s);
        }
    }

    const int cA = sub>>1, cB = sub&1;
    uint32_t aRow[MI], bRow[NJ2];
    #pragma unroll
    for(int it=0;it<MI;it++)
        aRow[it] = tiles + (uint32_t)((wm*WM + it*16 + (sub&1)*8 + i8)*128);
    #pragma unroll
    for(int jp=0;jp<NJ2;jp++)
        bRow[jp] = tiles + (uint32_t)(ABYTES + (wn*WN + jp*16 + (sub>>1)*8 + i8)*128);

    float acc[MI][NJ][4];
    #pragma unroll
    for(int i=0;i<MI;i++)
        #pragma unroll
        for(int j=0;j<NJ;j++)
            #pragma unroll
            for(int e=0;e<4;e++) acc[i][j][e] = 0.0f;

    uint32_t ahB[2][MI][4], bbB[2][NJ2][4];

    for(int c=0;c<NC;c++){
        int s = c % S;
        mbar_wait(mb + 8*s, (uint32_t)((c/S)&1));
        if(tid==0 && c+S-1 < NC){
            int s2 = (c+S-1)%S;
            mbar_expect(mb + 8*s2, STAGE);
            bulkcp(tiles + s2*STAGE,          AbBase + (size_t)(c+S-1)*16384, ABYTES, mb + 8*s2);
            bulkcp(tiles + s2*STAGE + ABYTES, BbBase + (size_t)(c+S-1)*16384, BBYTES, mb + 8*s2);
        }
        const uint32_t bufOff = (uint32_t)(s*STAGE);

        #define LD_FRAG(kk, p) do{                                                   \
            _Pragma("unroll")                                                        \
            for(int it_=0;it_<MI;it_++)                                              \
                ldsm4(ahB[p][it_], aRow[it_] + bufOff + (uint32_t)((((2*(kk) + cA) ^ i8))<<4)); \
            _Pragma("unroll")                                                        \
            for(int jp_=0;jp_<NJ2;jp_++)                                             \
                ldsm4(bbB[p][jp_], bRow[jp_] + bufOff + (uint32_t)((((2*(kk) + cB) ^ i8))<<4)); \
        }while(0)

        LD_FRAG(0, 0);
        #pragma unroll
        for(int kk=0;kk<4;kk++){
            const int cur = kk&1;
            if(kk<3) LD_FRAG(kk+1, cur^1);
            #pragma unroll
            for(int it=0;it<MI;it++)
                #pragma unroll
                for(int jt=0;jt<NJ;jt++){
                    const uint32_t* bf = bbB[cur][jt>>1];
                    int o = (jt&1)*2;
                    mma_f16(acc[it][jt], ahB[cur][it][0], ahB[cur][it][1],
                            ahB[cur][it][2], ahB[cur][it][3], bf[o], bf[o+1]);
                }
        }
        #undef LD_FRAG
        __syncthreads();
    }

    #pragma unroll
    for(int jt=0;jt<NJ;jt++){
        int i0 = ((colBase + wn*WN + jt*8)>>1) + t4;
        #pragma unroll
        for(int it=0;it<MI;it++){
            int r = rowBase + wm*WM + it*16 + g;
            float h0 = acc[it][jt][0], g0 = acc[it][jt][1];
            float h1 = acc[it][jt][2], g1 = acc[it][jt][3];
            float z0 = g0/(1.0f + __expf(-g0))*h0;
            float z1 = g1/(1.0f + __expf(-g1))*h1;
            float z0n = __shfl_xor_sync(0xffffffffu, z0, 1);
            float z1n = __shfl_xor_sync(0xffffffffu, z1, 1);
            if((t4 & 1) == 0){
                int j = i0>>1;
                Cv[cidx(r,   j, ncK)] = packh2(z0, z0n);
                Cv[cidx(r+8, j, ncK)] = packh2(z1, z1n);
            }
        }
    }
}

// ---------------- split column norms: 8-way row partials + finalize ----------------
__global__ void colnorm_part_k(const float* __restrict__ W, float* __restrict__ part,
                               int R, int C){
    int l = blockIdx.y;
    int c = blockIdx.x*256 + threadIdx.x;
    int sp = blockIdx.z;
    if(c >= C) return;
    const float* Wl = W + (size_t)l*R*C;
    int r0 = sp*(R>>3), r1 = r0 + (R>>3);
    float s = 0.0f;
    for(int r=r0;r<r1;r++){ float w = Wl[(size_t)r*C + c]; s += w*w; }
    part[((size_t)sp*NL + l)*DFFP + c] = s;
}
__global__ void colnorm_fin_k(const float* __restrict__ part, float* __restrict__ f, int C){
    int l = blockIdx.y;
    int c = blockIdx.x*256 + threadIdx.x;
    if(c >= C) return;
    float s = 0.0f;
    #pragma unroll
    for(int sp=0;sp<8;sp++) s += part[((size_t)sp*NL + l)*DFFP + c];
    f[(size_t)l*C + c] = l2fac(sqrtf(s));
}

// ---------------- fused norm + pack kernels ----------------
__global__ void wpack_qkv_k(const float* __restrict__ Wq, const float* __restrict__ Wk,
                            const float* __restrict__ Wv, int lbase,
                            uint32_t* __restrict__ dst){
    __shared__ float red[256];
    int rr = blockIdx.x + lbase*NQKV;
    int l = rr / NQKV, r = rr % NQKV;
    int which = r >> 10, rl = r & 1023;
    const float* W = (which==0) ? Wq : (which==1) ? Wk : Wv;
    const float4* sp = (const float4*)(W + ((size_t)l*Dm + rl)*Dm);
    float4 v = sp[threadIdx.x];
    float s = v.x*v.x + v.y*v.y + v.z*v.z + v.w*v.w;
    s = blocksum256(s, red);
    float f = l2fac(sqrtf(s));
    dst[cidx(rr, 2*threadIdx.x,   NCKD)] = packh2(v.x*f, v.y*f);
    dst[cidx(rr, 2*threadIdx.x+1, NCKD)] = packh2(v.z*f, v.w*f);
}
__global__ void wpack_o_k(const float* __restrict__ Wo, uint32_t* __restrict__ dst){
    int rr = blockIdx.x;
    const float4* sp = (const float4*)(Wo + (size_t)rr*Dm);
    float4 v = sp[threadIdx.x];
    dst[cidx(rr, 2*threadIdx.x,   NCKD)] = packh2(v.x, v.y);
    dst[cidx(rr, 2*threadIdx.x+1, NCKD)] = packh2(v.z, v.w);
}
__global__ void wpack_hg_k(const float* __restrict__ Wffh, const float* __restrict__ Wffg,
                           const float* __restrict__ hsc, const float* __restrict__ gsc,
                           uint32_t* __restrict__ dst){
    __shared__ float red[256];
    int rr = blockIdx.x;
    int l = rr / NHG, r = rr % NHG;
    int p = r >> 1, isG = r & 1;
    if(p >= DFFn){
        dst[cidx(rr, 2*threadIdx.x,   NCKD)] = 0u;
        dst[cidx(rr, 2*threadIdx.x+1, NCKD)] = 0u;
        return;
    }
    size_t sr = (size_t)l*DFFn + p;
    const float* W = isG ? (Wffg + sr*Dm) : (Wffh + sr*Dm);
    float sc = isG ? gsc[sr]*32.0f : hsc[sr];
    float4 v = ((const float4*)W)[threadIdx.x];
    float s = v.x*v.x + v.y*v.y + v.z*v.z + v.w*v.w;
    s = blocksum256(s, red);
    float f = l2fac(sqrtf(s))*sc;
    dst[cidx(rr, 2*threadIdx.x,   NCKD)] = packh2(v.x*f, v.y*f);
    dst[cidx(rr, 2*threadIdx.x+1, NCKD)] = packh2(v.z*f, v.w*f);
}
__global__ void wpack_fo_k(const float* __restrict__ Wffo, const float* __restrict__ fffo,
                           uint32_t* __restrict__ dst){
    int rr = blockIdx.x;
    int l = rr / Dm, rl = rr % Dm;
    const float2* sp = (const float2*)(Wffo + ((size_t)l*Dm + rl)*DFFn);
    const float* ks = fffo + (size_t)l*DFFn;
    for(int j=threadIdx.x;j<UF;j+=256){
        float x0=0.0f, x1=0.0f;
        if(2*j < DFFn){ float2 vv = sp[j]; x0 = vv.x*ks[2*j]; x1 = vv.y*ks[2*j+1]; }
        dst[cidx(rr, j, NCKF)] = packh2(x0, x1);
    }
}
__global__ void wpack_log_k(const float* __restrict__ Wl, const float* __restrict__ lsc,
                            uint32_t* __restrict__ dst){
    __shared__ float red[256];
    int r = blockIdx.x;
    const float4* sp = (const float4*)(Wl + (size_t)r*Dm);
    float4 v = sp[threadIdx.x];
    float s = v.x*v.x + v.y*v.y + v.z*v.z + v.w*v.w;
    s = blocksum256(s, red);
    float f = l2fac(sqrtf(s))*lsc[r]*32.0f;
    dst[cidx(r, 2*threadIdx.x,   NCKD)] = packh2(v.x*f, v.y*f);
    dst[cidx(r, 2*threadIdx.x+1, NCKD)] = packh2(v.z*f, v.w*f);
}

// ---------------- embedding ----------------
__global__ void embed_k(const int* __restrict__ ids, const float* __restrict__ W_emb,
                        float* __restrict__ x, uint32_t* __restrict__ xp2){
    __shared__ float red[256];
    int m = blockIdx.x, t = threadIdx.x;
    int tok = ids[m];
    const float2* row2 = (const float2*)(W_emb + (size_t)tok*Dm);
    float2 a = row2[t], b = row2[t+256];
    float s = a.x*a.x + a.y*a.y + b.x*b.x + b.y*b.y;
    s = blocksum256(s, red);
    float f = l2fac(sqrtf(s));
    a.x*=f; a.y*=f; b.x*=f; b.y*=f;
    float2* x2 = (float2*)(x + (size_t)m*Dm);
    x2[t] = a; x2[t+256] = b;
    xp2[cidx(m, t,     NCKD)] = packh2(a.x, a.y);
    xp2[cidx(m, t+256, NCKD)] = packh2(b.x, b.y);
}

// ---------------- fused attn-prep + delta rule (256 threads, 4-way k-split) ----------------
#define DCH 32
__global__ void __launch_bounds__(256)
delta_k(const float* __restrict__ qkv, const float* __restrict__ qs_l,
        const float* __restrict__ Wbeta, const float* __restrict__ bscale,
        int l, int is_l0, float* __restrict__ v0h,
        uint32_t* __restrict__ op2, const float* __restrict__ fWo){
    int bh = blockIdx.x;
    int b = bh / NH, h = bh % NH;
    int t = threadIdx.x;                 // 0..255
    int warp = t>>5, lane = t&31;
    int col = t>>2, par = t&3;           // 4 threads per state column

    float wb0 = Wbeta[l*DHd + lane], wb1 = Wbeta[l*DHd + lane + 32];
    float wfac = l2fac(sqrtf(warpsum(wb0*wb0 + wb1*wb1))) * (bscale[l]*0.1f);
    float wbn0 = wb0*wfac, wbn1 = wb1*wfac;
    float qsc0 = qs_l[h*DHd + lane]*1024.0f, qsc1 = qs_l[h*DHd + lane + 32]*1024.0f;

    float St[16];                        // state rows 4j+par, column col
    #pragma unroll
    for(int i=0;i<16;i++) St[i] = 0.0f;

    __shared__ float ks[DCH*DHd];
    __shared__ float qs[DCH*DHd];
    __shared__ float vs[DCH*DHd];
    __shared__ float bs[DCH];

    float fo = fWo[h*DHd + col];

    for(int c0=0;c0<SEQn;c0+=DCH){
        __syncthreads();
        // staging: 8 warps x 4 tokens
        #pragma unroll
        for(int j=0;j<4;j++){
            int i = warp + 8*j;
            int m = b*SEQn + c0 + i;
            size_t src = (size_t)m*NQKV + h*DHd;
            float q0=qkv[src+lane],       q1=qkv[src+lane+32];
            float k0=qkv[src+Dm+lane],    k1=qkv[src+Dm+lane+32];
            float v0=qkv[src+2*Dm+lane],  v1=qkv[src+2*Dm+lane+32];
            float fq = l2fac(sqrtf(warpsum(q0*q0 + q1*q1)));
            float fk = l2fac(sqrtf(warpsum(k0*k0 + k1*k1)));
            float kn0 = k0*fk, kn1 = k1*fk;
            float bd = warpsum(kn0*wbn0 + kn1*wbn1);
            size_t vdst = ((size_t)bh*SEQn + c0 + i)*DHd;
            float vv0, vv1;
            if(is_l0){ vv0=v0; vv1=v1; v0h[vdst+lane]=v0; v0h[vdst+lane+32]=v1; }
            else     { vv0=0.5f*(v0 + v0h[vdst+lane]); vv1=0.5f*(v1 + v0h[vdst+lane+32]); }
            qs[i*DHd+lane] = q0*fq*qsc0;  qs[i*DHd+lane+32] = q1*fq*qsc1;
            ks[i*DHd+lane] = kn0;         ks[i*DHd+lane+32] = kn1;
            vs[i*DHd+lane] = vv0;         vs[i*DHd+lane+32] = vv1;
            if(lane==0) bs[i] = 1.0f/(1.0f + __expf(-bd));
        }
        __syncthreads();
        for(int tt=0;tt<DCH;tt++){
            const float* kt = &ks[tt*DHd];
            const float* qt = &qs[tt*DHd];
            float p0=0,p1=0,p2=0,p3=0;
            #pragma unroll
            for(int j=0;j<16;j+=4){
                p0 += kt[4*j+par]*St[j];
                p1 += kt[4*(j+1)+par]*St[j+1];
                p2 += kt[4*(j+2)+par]*St[j+2];
                p3 += kt[4*(j+3)+par]*St[j+3];
            }
            float kS = (p0+p1)+(p2+p3);
            kS += __shfl_xor_sync(0xffffffffu, kS, 1);
            kS += __shfl_xor_sync(0xffffffffu, kS, 2);
            float dlt = bs[tt]*(vs[tt*DHd + col] - kS);
            float o0=0,o1=0,o2=0,o3=0;
            #pragma unroll
            for(int j=0;j<16;j+=4){
                St[j]   += kt[4*j+par]*dlt;     o0 += qt[4*j+par]*St[j];
                St[j+1] += kt[4*(j+1)+par]*dlt; o1 += qt[4*(j+1)+par]*St[j+1];
                St[j+2] += kt[4*(j+2)+par]*dlt; o2 += qt[4*(j+2)+par]*St[j+2];
                St[j+3] += kt[4*(j+3)+par]*dlt; o3 += qt[4*(j+3)+par]*St[j+3];
            }
            float o = (o0+o1)+(o2+o3);
            o += __shfl_xor_sync(0xffffffffu, o, 1);
            o += __shfl_xor_sync(0xffffffffu, o, 2);
            o *= fo;
            float oN = __shfl_down_sync(0xffffffffu, o, 4);
            if((t & 7) == 0){
                int m = b*SEQn + c0 + tt;
                op2[cidx(m, h*32 + (col>>1), NCKD)] = packh2(o, oN);
            }
        }
    }
}

// ---------------- residual ----------------
__global__ void resid_k(float* __restrict__ x, const float* __restrict__ o,
                        const float* __restrict__ alpha, uint32_t* __restrict__ xp2){
    __shared__ float red[256];
    int m = blockIdx.x, t = threadIdx.x;
    const float2* o2 = (const float2*)(o + (size_t)m*Dm);
    float2 oa = o2[t], ob = o2[t+256];
    float s = oa.x*oa.x + oa.y*oa.y + ob.x*ob.x + ob.y*ob.y;
    s = blocksum256(s, red);
    float fh = l2fac(sqrtf(s));
    float2* x2 = (float2*)(x + (size_t)m*Dm);
    float2 xa = x2[t], xb = x2[t+256];
    const float2* al2 = (const float2*)alpha;
    float2 aa = al2[t], ab = al2[t+256];
    float ya0 = xa.x + aa.x*8.0f*(oa.x*fh - xa.x);
    float ya1 = xa.y + aa.y*8.0f*(oa.y*fh - xa.y);
    float yb0 = xb.x + ab.x*8.0f*(ob.x*fh - xb.x);
    float yb1 = xb.y + ab.y*8.0f*(ob.y*fh - xb.y);
    float s2 = ya0*ya0 + ya1*ya1 + yb0*yb0 + yb1*yb1;
    s2 = blocksum256(s2, red);
    float f2 = l2fac(sqrtf(s2));
    ya0*=f2; ya1*=f2; yb0*=f2; yb1*=f2;
    x2[t]     = make_float2(ya0, ya1);
    x2[t+256] = make_float2(yb0, yb1);
    xp2[cidx(m, t,     NCKD)] = packh2(ya0, ya1);
    xp2[cidx(m, t+256, NCKD)] = packh2(yb0, yb1);
}

// ---------------- host ----------------
struct GraphAux {
    cudaStream_t s1;
    cudaEvent_t evRoot, evCn1, evO, evQ, evHg, evFo, evLog;
    GraphAux(){
        cudaStreamCreateWithFlags(&s1, cudaStreamNonBlocking);
        cudaEventCreateWithFlags(&evRoot, cudaEventDisableTiming);
        cudaEventCreateWithFlags(&evCn1,  cudaEventDisableTiming);
        cudaEventCreateWithFlags(&evO,    cudaEventDisableTiming);
        cudaEventCreateWithFlags(&evQ,    cudaEventDisableTiming);
        cudaEventCreateWithFlags(&evHg,   cudaEventDisableTiming);
        cudaEventCreateWithFlags(&evFo,   cudaEventDisableTiming);
        cudaEventCreateWithFlags(&evLog,  cudaEventDisableTiming);
    }
};
static GraphAux g_aux;

template<typename T> static void* symaddr(T& s){
    void* p = nullptr; cudaGetSymbolAddress(&p, s); return p;
}

extern "C" void kernel_launch(void* const* d_in, const int* in_sizes, int n_in,
                              void* d_out, int out_size){
    (void)in_sizes; (void)n_in; (void)out_size;
    const int*   ids        = (const int*)  d_in[0];
    const float* W_emb      = (const float*)d_in[2];
    const float* Wq         = (const float*)d_in[3];
    const float* Wk         = (const float*)d_in[4];
    const float* Wv         = (const float*)d_in[5];
    const float* Wbeta      = (const float*)d_in[6];
    const float* Wo         = (const float*)d_in[7];
    const float* Wffh       = (const float*)d_in[8];
    const float* Wffg       = (const float*)d_in[9];
    const float* Wffo       = (const float*)d_in[10];
    const float* qk_scale   = (const float*)d_in[11];
    const float* beta_scale = (const float*)d_in[12];
    const float* attn_alpha = (const float*)d_in[13];
    const float* ff_alpha   = (const float*)d_in[14];
    const float* ffh_scale  = (const float*)d_in[15];
    const float* ffg_scale  = (const float*)d_in[16];
    const float* W_logits   = (const float*)d_in[17];
    const float* logit_scale= (const float*)d_in[18];
    float* out = (float*)d_out;

    float* x     = (float*)symaddr(g_x);
    float* qkv   = (float*)symaddr(g_qkv);
    float* obuf  = (float*)symaddr(g_obuf);
    float* v0h   = (float*)symaddr(g_v0h);
    float* fo    = (float*)symaddr(g_fo);
    float* fffo  = (float*)symaddr(g_fffo);
    float* part  = (float*)symaddr(g_part);
    uint32_t* xp2   = (uint32_t*)symaddr(g_xp2);
    uint32_t* op2   = (uint32_t*)symaddr(g_op2);
    uint32_t* zp2   = (uint32_t*)symaddr(g_zp2);
    uint32_t* wqkv2 = (uint32_t*)symaddr(g_wqkv2);
    uint32_t* wo2   = (uint32_t*)symaddr(g_wo2);
    uint32_t* whg2  = (uint32_t*)symaddr(g_whg2);
    uint32_t* wfo2  = (uint32_t*)symaddr(g_wfo2);
    uint32_t* wl2   = (uint32_t*)symaddr(g_wl2);

    cudaFuncSetAttribute(gemm_mma_k<128,128,64,32,3,0>, cudaFuncAttributeMaxDynamicSharedMemorySize, 99328);
    cudaFuncSetAttribute(gemm_hg_k<128,64,32,32,3>,     cudaFuncAttributeMaxDynamicSharedMemorySize, 74752);
    cudaFuncSetAttribute(gemm_mma_k<64,64,32,16,4,0>,   cudaFuncAttributeMaxDynamicSharedMemorySize, 66560);

    cudaStream_t s1 = g_aux.s1;

    cudaEventRecord(g_aux.evRoot, 0);
    cudaStreamWaitEvent(s1, g_aux.evRoot, 0);

    // side stream: deferred packing, earliest-consumer order
    colnorm_part_k<<<dim3(Dm/256, NL, 8), 256, 0, s1>>>(Wo, part, Dm, Dm);
    colnorm_fin_k<<<dim3(Dm/256, NL), 256, 0, s1>>>(part, fo, Dm);
    cudaEventRecord(g_aux.evCn1, s1);
    wpack_o_k<<<NL*Dm, 256, 0, s1>>>(Wo, wo2);
    cudaEventRecord(g_aux.evO, s1);
    wpack_qkv_k<<<3*NQKV, 256, 0, s1>>>(Wq, Wk, Wv, 1, wqkv2);
    cudaEventRecord(g_aux.evQ, s1);
    wpack_hg_k<<<NL*NHG, 256, 0, s1>>>(Wffh, Wffg, ffh_scale, ffg_scale, whg2);
    cudaEventRecord(g_aux.evHg, s1);
    colnorm_part_k<<<dim3((DFFn+255)/256, NL, 8), 256, 0, s1>>>(Wffo, part, Dm, DFFn);
    colnorm_fin_k<<<dim3((DFFn+255)/256, NL), 256, 0, s1>>>(part, fffo, DFFn);
    wpack_fo_k<<<NL*Dm, 256, 0, s1>>>(Wffo, fffo, wfo2);
    cudaEventRecord(g_aux.evFo, s1);
    wpack_log_k<<<NV, 256, 0, s1>>>(W_logits, logit_scale, wl2);
    cudaEventRecord(g_aux.evLog, s1);

    // main stream
    wpack_qkv_k<<<NQKV, 256>>>(Wq, Wk, Wv, 0, wqkv2);
    embed_k<<<MT, 256>>>(ids, W_emb, x, xp2);

    for(int l=0;l<NL;l++){
        if(l==1) cudaStreamWaitEvent(0, g_aux.evQ, 0);
        gemm_mma_k<128,128,64,32,3,0><<<dim3(8, NQKV/128), 256, 99328>>>(
            xp2, wqkv2 + (size_t)l*NQKV*UD, qkv, NQKV, Dm);
        if(l==0) cudaStreamWaitEvent(0, g_aux.evCn1, 0);
        delta_k<<<NB*NH, 256>>>(qkv, qk_scale + l*Dm, Wbeta, beta_scale, l,
                                (l==0)?1:0, v0h, op2, fo + l*Dm);
        if(l==0) cudaStreamWaitEvent(0, g_aux.evO, 0);
        gemm_mma_k<64,64,32,16,4,0><<<dim3(16, 16), 256, 66560>>>(
            op2, wo2 + (size_t)l*Dm*UD, obuf, Dm, Dm);
        resid_k<<<MT, 256>>>(x, obuf, attn_alpha + l*Dm, xp2);
        if(l==0) cudaStreamWaitEvent(0, g_aux.evHg, 0);
        gemm_hg_k<128,64,32,32,3><<<dim3(8, NHG/64), 256, 74752>>>(
            xp2, whg2 + (size_t)l*NHG*UD, zp2, NCKF, Dm);
        if(l==0) cudaStreamWaitEvent(0, g_aux.evFo, 0);
        gemm_mma_k<64,64,32,16,4,0><<<dim3(16, 16), 256, 66560>>>(
            zp2, wfo2 + (size_t)l*Dm*UF, obuf, Dm, DFFP);
        resid_k<<<MT, 256>>>(x, obuf, ff_alpha + l*Dm, xp2);
    }
    cudaStreamWaitEvent(0, g_aux.evLog, 0);
    gemm_mma_k<128,128,64,32,3,0><<<dim3(8, NV/128), 256, 99328>>>(
        xp2, wl2, out, NV, Dm);
}

// round 16
// speedup vs baseline: 1.2513x; 1.0516x over previous
#include <cuda_runtime.h>
#include <cuda_bf16.h>
#include <cuda_fp16.h>
#include <math.h>
#include <stdint.h>

#define Dm    1024
#define SEQn  512
#define NB    2
#define NH    16
#define DHd   64
#define DFFn  2730
#define DFFP  2816
#define NV    32000
#define NL    4
#define MT    1024
#define NQKV  3072
#define NHG   5632
#define UD    512
#define UF    1408
#define NCKD  16
#define NCKF  44

// ---------------- fp32 scratch ----------------
__device__ float g_x[MT*Dm];
__device__ float g_qkv[MT*NQKV];
__device__ float g_obuf[MT*Dm];
__device__ float g_v0h[NB*NH*SEQn*DHd];
__device__ float g_fo[NL*Dm];
__device__ float g_fffo[NL*DFFn];
__device__ float g_part[8*NL*DFFP];

// ---------------- packed fp16 buffers, chunked pre-swizzled layout ----------------
__device__ uint32_t g_xp2 [MT*UD];
__device__ uint32_t g_op2 [MT*UD];
__device__ uint32_t g_zp2 [MT*UF];
__device__ uint32_t g_wqkv2[(size_t)NL*NQKV*UD];
__device__ uint32_t g_wo2  [(size_t)NL*Dm*UD];
__device__ uint32_t g_whg2 [(size_t)NL*NHG*UD];
__device__ uint32_t g_wfo2 [(size_t)NL*Dm*UF];
__device__ uint32_t g_wl2  [(size_t)NV*UD];

static __device__ __forceinline__ size_t cidx(int gr, int j, int ncK){
    return ((size_t)(gr>>7)*ncK + (j>>5))*4096 + (size_t)(gr&127)*32
         + ((((j>>2)&7) ^ (gr&7))<<2) + (j&3);
}

// ---------------- scalar helpers ----------------
static __device__ __forceinline__ float l2fac(float n){
    float tgt = fminf(fmaxf(n, 1.0f - 1e-5f), 1.0f + 1e-5f);
    return 1.0f / fmaxf(n / tgt, 1e-10f);
}
static __device__ __forceinline__ float warpsum(float v){
    #pragma unroll
    for(int o=16;o>0;o>>=1) v += __shfl_xor_sync(0xffffffffu, v, o);
    return v;
}
// fast block reduction: 2 syncthreads instead of 16
static __device__ __forceinline__ float blocksum256(float v, float* red){
    v = warpsum(v);
    if((threadIdx.x&31)==0) red[threadIdx.x>>5] = v;
    __syncthreads();
    float s = ((red[0]+red[1])+(red[2]+red[3])) + ((red[4]+red[5])+(red[6]+red[7]));
    __syncthreads();
    return s;
}
static __device__ __forceinline__ uint32_t packh2(float x0, float x1){
    return (uint32_t)__half_as_ushort(__float2half_rn(x0))
         | ((uint32_t)__half_as_ushort(__float2half_rn(x1))<<16);
}

// ---------------- bulk-copy / mbarrier / ldmatrix / mma primitives ----------------
static __device__ __forceinline__ void mbar_init(uint32_t a, uint32_t c){
    asm volatile("mbarrier.init.shared.b64 [%0], %1;" :: "r"(a), "r"(c) : "memory");
}
static __device__ __forceinline__ void mbar_expect(uint32_t a, uint32_t bytes){
    asm volatile("mbarrier.arrive.expect_tx.shared.b64 _, [%0], %1;"
                 :: "r"(a), "r"(bytes) : "memory");
}
static __device__ __forceinline__ void mbar_wait(uint32_t a, uint32_t ph){
    asm volatile("{\n\t.reg .pred P;\n\t"
        "WL_%=:\n\t"
        "mbarrier.try_wait.parity.shared.b64 P, [%0], %1;\n\t"
        "@P bra.uni WD_%=;\n\t"
        "bra.uni WL_%=;\n\t"
        "WD_%=:\n\t}"
        :: "r"(a), "r"(ph) : "memory");
}
static __device__ __forceinline__ void bulkcp(uint32_t dst, const void* src, uint32_t bytes,
                                              uint32_t mbar){
    asm volatile("cp.async.bulk.shared::cluster.global.mbarrier::complete_tx::bytes "
                 "[%0], [%1], %2, [%3];"
                 :: "r"(dst), "l"(src), "r"(bytes), "r"(mbar) : "memory");
}
static __device__ __forceinline__ void ldsm4(uint32_t* r, uint32_t a){
    asm volatile("ldmatrix.sync.aligned.m8n8.x4.shared.b16 {%0,%1,%2,%3}, [%4];"
        : "=r"(r[0]),"=r"(r[1]),"=r"(r[2]),"=r"(r[3]) : "r"(a));
}
static __device__ __forceinline__ void mma_f16(float* c,
        uint32_t a0, uint32_t a1, uint32_t a2, uint32_t a3, uint32_t b0, uint32_t b1){
    asm volatile("mma.sync.aligned.m16n8k16.row.col.f32.f16.f16.f32 "
                 "{%0,%1,%2,%3},{%4,%5,%6,%7},{%8,%9},{%0,%1,%2,%3};"
                 : "+f"(c[0]), "+f"(c[1]), "+f"(c[2]), "+f"(c[3])
                 : "r"(a0), "r"(a1), "r"(a2), "r"(a3), "r"(b0), "r"(b1));
}

// ---------------- bulk-copy mma GEMM: C[M,N] = A @ B^T (fp32 out) ----------------
template<int BM,int BN,int WM,int WN,int S,int EPI>
__global__ void __launch_bounds__(256, 2)
gemm_mma_k(const uint32_t* __restrict__ Au, const uint32_t* __restrict__ Bu,
           void* __restrict__ Cv, int ldc, int Ks){
    constexpr int ABYTES = BM*128, BBYTES = BN*128, STAGE = ABYTES+BBYTES;
    constexpr int WNW = BN/WN;
    constexpr int MI = WM/16, NJ = WN/8, NJ2 = NJ/2;

    extern __shared__ char sm[];
    uint32_t smBase = (uint32_t)__cvta_generic_to_shared(sm);
    uint32_t mb = smBase;
    uint32_t tiles = smBase + 1024;

    const int tid = threadIdx.x, warp = tid>>5, lane = tid&31;
    const int wm = warp / WNW, wn = warp % WNW;
    const int i8 = lane&7, sub = lane>>3;
    const int g = lane>>2, t4 = lane&3;
    const int rowBase = blockIdx.x*BM, colBase = blockIdx.y*BN;
    const int NC = Ks>>6;

    const char* AbBase = (const char*)Au + ((size_t)(rowBase>>7)*NC)*16384
                       + (size_t)((rowBase>>6)&1)*8192;
    const char* BbBase = (const char*)Bu + ((size_t)(colBase>>7)*NC)*16384
                       + (size_t)((colBase>>6)&1)*8192;

    if(tid==0){
        #pragma unroll
        for(int s=0;s<S;s++) mbar_init(mb + 8*s, 1);
    }
    __syncthreads();
    if(tid==0){
        #pragma unroll
        for(int s=0;s<S-1;s++){
            mbar_expect(mb + 8*s, STAGE);
            bulkcp(tiles + s*STAGE,          AbBase + (size_t)s*16384, ABYTES, mb + 8*s);
            bulkcp(tiles + s*STAGE + ABYTES, BbBase + (size_t)s*16384, BBYTES, mb + 8*s);
        }
    }

    const int cA = sub>>1, cB = sub&1;
    uint32_t aRow[MI], bRow[NJ2];
    #pragma unroll
    for(int it=0;it<MI;it++)
        aRow[it] = tiles + (uint32_t)((wm*WM + it*16 + (sub&1)*8 + i8)*128);
    #pragma unroll
    for(int jp=0;jp<NJ2;jp++)
        bRow[jp] = tiles + (uint32_t)(ABYTES + (wn*WN + jp*16 + (sub>>1)*8 + i8)*128);

    float acc[MI][NJ][4];
    #pragma unroll
    for(int i=0;i<MI;i++)
        #pragma unroll
        for(int j=0;j<NJ;j++)
            #pragma unroll
            for(int e=0;e<4;e++) acc[i][j][e] = 0.0f;

    uint32_t ahB[2][MI][4], bbB[2][NJ2][4];

    for(int c=0;c<NC;c++){
        int s = c % S;
        mbar_wait(mb + 8*s, (uint32_t)((c/S)&1));
        if(tid==0 && c+S-1 < NC){
            int s2 = (c+S-1)%S;
            mbar_expect(mb + 8*s2, STAGE);
            bulkcp(tiles + s2*STAGE,          AbBase + (size_t)(c+S-1)*16384, ABYTES, mb + 8*s2);
            bulkcp(tiles + s2*STAGE + ABYTES, BbBase + (size_t)(c+S-1)*16384, BBYTES, mb + 8*s2);
        }
        const uint32_t bufOff = (uint32_t)(s*STAGE);

        #define LD_FRAG(kk, p) do{                                                   \
            _Pragma("unroll")                                                        \
            for(int it_=0;it_<MI;it_++)                                              \
                ldsm4(ahB[p][it_], aRow[it_] + bufOff + (uint32_t)((((2*(kk) + cA) ^ i8))<<4)); \
            _Pragma("unroll")                                                        \
            for(int jp_=0;jp_<NJ2;jp_++)                                             \
                ldsm4(bbB[p][jp_], bRow[jp_] + bufOff + (uint32_t)((((2*(kk) + cB) ^ i8))<<4)); \
        }while(0)

        LD_FRAG(0, 0);
        #pragma unroll
        for(int kk=0;kk<4;kk++){
            const int cur = kk&1;
            if(kk<3) LD_FRAG(kk+1, cur^1);
            #pragma unroll
            for(int it=0;it<MI;it++)
                #pragma unroll
                for(int jt=0;jt<NJ;jt++){
                    const uint32_t* bf = bbB[cur][jt>>1];
                    int o = (jt&1)*2;
                    mma_f16(acc[it][jt], ahB[cur][it][0], ahB[cur][it][1],
                            ahB[cur][it][2], ahB[cur][it][3], bf[o], bf[o+1]);
                }
        }
        #undef LD_FRAG
        __syncthreads();
    }

    float* C = (float*)Cv;
    #pragma unroll
    for(int jt=0;jt<NJ;jt++){
        int c = colBase + wn*WN + jt*8 + t4*2;
        #pragma unroll
        for(int it=0;it<MI;it++){
            int r = rowBase + wm*WM + it*16 + g;
            *(float2*)(C + (size_t)r*ldc + c)     = make_float2(acc[it][jt][0], acc[it][jt][1]);
            *(float2*)(C + (size_t)(r+8)*ldc + c) = make_float2(acc[it][jt][2], acc[it][jt][3]);
        }
    }
}

// hg GEMM: (h,g) col pairs -> packed fp16 silu(g)*h into chunked C
template<int BM,int BN,int WM,int WN,int S>
__global__ void __launch_bounds__(256, 2)
gemm_hg_k(const uint32_t* __restrict__ Au, const uint32_t* __restrict__ Bu,
          uint32_t* __restrict__ Cv, int ncK, int Ks){
    constexpr int ABYTES = BM*128, BBYTES = BN*128, STAGE = ABYTES+BBYTES;
    constexpr int WNW = BN/WN;
    constexpr int MI = WM/16, NJ = WN/8, NJ2 = NJ/2;

    extern __shared__ char sm[];
    uint32_t smBase = (uint32_t)__cvta_generic_to_shared(sm);
    uint32_t mb = smBase;
    uint32_t tiles = smBase + 1024;

    const int tid = threadIdx.x, warp = tid>>5, lane = tid&31;
    const int wm = warp / WNW, wn = warp % WNW;
    const int i8 = lane&7, sub = lane>>3;
    const int g = lane>>2, t4 = lane&3;
    const int rowBase = blockIdx.x*BM, colBase = blockIdx.y*BN;
    const int NC = Ks>>6;

    const char* AbBase = (const char*)Au + ((size_t)(rowBase>>7)*NC)*16384
                       + (size_t)((rowBase>>6)&1)*8192;
    const char* BbBase = (const char*)Bu + ((size_t)(colBase>>7)*NC)*16384
                       + (size_t)((colBase>>6)&1)*8192;

    if(tid==0){
        #pragma unroll
        for(int s=0;s<S;s++) mbar_init(mb + 8*s, 1);
    }
    __syncthreads();
    if(tid==0){
        #pragma unroll
        for(int s=0;s<S-1;s++){
            mbar_expect(mb + 8*s, STAGE);
            bulkcp(tiles + s*STAGE,          AbBase + (size_t)s*16384, ABYTES, mb + 8*s);
            bulkcp(tiles + s*STAGE + ABYTES, BbBase + (size_t)s*16384, BBYTES, mb + 8*s);
        }
    }

    const int cA = sub>>1, cB = sub&1;
    uint32_t aRow[MI], bRow[NJ2];
    #pragma unroll
    for(int it=0;it<MI;it++)
        aRow[it] = tiles + (uint32_t)((wm*WM + it*16 + (sub&1)*8 + i8)*128);
    #pragma unroll
    for(int jp=0;jp<NJ2;jp++)
        bRow[jp] = tiles + (uint32_t)(ABYTES + (wn*WN + jp*16 + (sub>>1)*8 + i8)*128);

    float acc[MI][NJ][4];
    #pragma unroll
    for(int i=0;i<MI;i++)
        #pragma unroll
        for(int j=0;j<NJ;j++)
            #pragma unroll
            for(int e=0;e<4;e++) acc[i][j][e] = 0.0f;

    uint32_t ahB[2][MI][4], bbB[2][NJ2][4];

    for(int c=0;c<NC;c++){
        int s = c % S;
        mbar_wait(mb + 8*s, (uint32_t)((c/S)&1));
        if(tid==0 && c+S-1 < NC){
            int s2 = (c+S-1)%S;
            mbar_expect(mb + 8*s2, STAGE);
            bulkcp(tiles + s2*STAGE,          AbBase + (size_t)(c+S-1)*16384, ABYTES, mb + 8*s2);
            bulkcp(tiles + s2*STAGE + ABYTES, BbBase + (size_t)(c+S-1)*16384, BBYTES, mb + 8*s2);
        }
        const uint32_t bufOff = (uint32_t)(s*STAGE);

        #define LD_FRAG(kk, p) do{                                                   \
            _Pragma("unroll")                                                        \
            for(int it_=0;it_<MI;it_++)                                              \
                ldsm4(ahB[p][it_], aRow[it_] + bufOff + (uint32_t)((((2*(kk) + cA) ^ i8))<<4)); \
            _Pragma("unroll")                                                        \
            for(int jp_=0;jp_<NJ2;jp_++)                                             \
                ldsm4(bbB[p][jp_], bRow[jp_] + bufOff + (uint32_t)((((2*(kk) + cB) ^ i8))<<4)); \
        }while(0)

        LD_FRAG(0, 0);
        #pragma unroll
        for(int kk=0;kk<4;kk++){
            const int cur = kk&1;
            if(kk<3) LD_FRAG(kk+1, cur^1);
            #pragma unroll
            for(int it=0;it<MI;it++)
                #pragma unroll
                for(int jt=0;jt<NJ;jt++){
                    const uint32_t* bf = bbB[cur][jt>>1];
                    int o = (jt&1)*2;
                    mma_f16(acc[it][jt], ahB[cur][it][0], ahB[cur][it][1],
                            ahB[cur][it][2], ahB[cur][it][3], bf[o], bf[o+1]);
                }
        }
        #undef LD_FRAG
        __syncthreads();
    }

    #pragma unroll
    for(int jt=0;jt<NJ;jt++){
        int i0 = ((colBase + wn*WN + jt*8)>>1) + t4;
        #pragma unroll
        for(int it=0;it<MI;it++){
            int r = rowBase + wm*WM + it*16 + g;
            float h0 = acc[it][jt][0], g0 = acc[it][jt][1];
            float h1 = acc[it][jt][2], g1 = acc[it][jt][3];
            float z0 = g0/(1.0f + __expf(-g0))*h0;
            float z1 = g1/(1.0f + __expf(-g1))*h1;
            float z0n = __shfl_xor_sync(0xffffffffu, z0, 1);
            float z1n = __shfl_xor_sync(0xffffffffu, z1, 1);
            if((t4 & 1) == 0){
                int j = i0>>1;
                Cv[cidx(r,   j, ncK)] = packh2(z0, z0n);
                Cv[cidx(r+8, j, ncK)] = packh2(z1, z1n);
            }
        }
    }
}

// ---------------- split column norms: 8-way row partials + finalize ----------------
__global__ void colnorm_part_k(const float* __restrict__ W, float* __restrict__ part,
                               int R, int C){
    int l = blockIdx.y;
    int c = blockIdx.x*256 + threadIdx.x;
    int sp = blockIdx.z;
    if(c >= C) return;
    const float* Wl = W + (size_t)l*R*C;
    int r0 = sp*(R>>3), r1 = r0 + (R>>3);
    float s = 0.0f;
    for(int r=r0;r<r1;r++){ float w = Wl[(size_t)r*C + c]; s += w*w; }
    part[((size_t)sp*NL + l)*DFFP + c] = s;
}
__global__ void colnorm_fin_k(const float* __restrict__ part, float* __restrict__ f, int C){
    int l = blockIdx.y;
    int c = blockIdx.x*256 + threadIdx.x;
    if(c >= C) return;
    float s = 0.0f;
    #pragma unroll
    for(int sp=0;sp<8;sp++) s += part[((size_t)sp*NL + l)*DFFP + c];
    f[(size_t)l*C + c] = l2fac(sqrtf(s));
}

// ---------------- fused norm + pack kernels ----------------
__global__ void wpack_qkv_k(const float* __restrict__ Wq, const float* __restrict__ Wk,
                            const float* __restrict__ Wv, int lbase,
                            uint32_t* __restrict__ dst){
    __shared__ float red[8];
    int rr = blockIdx.x + lbase*NQKV;
    int l = rr / NQKV, r = rr % NQKV;
    int which = r >> 10, rl = r & 1023;
    const float* W = (which==0) ? Wq : (which==1) ? Wk : Wv;
    const float4* sp = (const float4*)(W + ((size_t)l*Dm + rl)*Dm);
    float4 v = sp[threadIdx.x];
    float s = v.x*v.x + v.y*v.y + v.z*v.z + v.w*v.w;
    s = blocksum256(s, red);
    float f = l2fac(sqrtf(s));
    dst[cidx(rr, 2*threadIdx.x,   NCKD)] = packh2(v.x*f, v.y*f);
    dst[cidx(rr, 2*threadIdx.x+1, NCKD)] = packh2(v.z*f, v.w*f);
}
__global__ void wpack_o_k(const float* __restrict__ Wo, uint32_t* __restrict__ dst){
    int rr = blockIdx.x;
    const float4* sp = (const float4*)(Wo + (size_t)rr*Dm);
    float4 v = sp[threadIdx.x];
    dst[cidx(rr, 2*threadIdx.x,   NCKD)] = packh2(v.x, v.y);
    dst[cidx(rr, 2*threadIdx.x+1, NCKD)] = packh2(v.z, v.w);
}
__global__ void wpack_hg_k(const float* __restrict__ Wffh, const float* __restrict__ Wffg,
                           const float* __restrict__ hsc, const float* __restrict__ gsc,
                           uint32_t* __restrict__ dst){
    __shared__ float red[8];
    int rr = blockIdx.x;
    int l = rr / NHG, r = rr % NHG;
    int p = r >> 1, isG = r & 1;
    if(p >= DFFn){
        dst[cidx(rr, 2*threadIdx.x,   NCKD)] = 0u;
        dst[cidx(rr, 2*threadIdx.x+1, NCKD)] = 0u;
        return;
    }
    size_t sr = (size_t)l*DFFn + p;
    const float* W = isG ? (Wffg + sr*Dm) : (Wffh + sr*Dm);
    float sc = isG ? gsc[sr]*32.0f : hsc[sr];
    float4 v = ((const float4*)W)[threadIdx.x];
    float s = v.x*v.x + v.y*v.y + v.z*v.z + v.w*v.w;
    s = blocksum256(s, red);
    float f = l2fac(sqrtf(s))*sc;
    dst[cidx(rr, 2*threadIdx.x,   NCKD)] = packh2(v.x*f, v.y*f);
    dst[cidx(rr, 2*threadIdx.x+1, NCKD)] = packh2(v.z*f, v.w*f);
}
__global__ void wpack_fo_k(const float* __restrict__ Wffo, const float* __restrict__ fffo,
                           uint32_t* __restrict__ dst){
    int rr = blockIdx.x;
    int l = rr / Dm, rl = rr % Dm;
    const float2* sp = (const float2*)(Wffo + ((size_t)l*Dm + rl)*DFFn);
    const float* ks = fffo + (size_t)l*DFFn;
    for(int j=threadIdx.x;j<UF;j+=256){
        float x0=0.0f, x1=0.0f;
        if(2*j < DFFn){ float2 vv = sp[j]; x0 = vv.x*ks[2*j]; x1 = vv.y*ks[2*j+1]; }
        dst[cidx(rr, j, NCKF)] = packh2(x0, x1);
    }
}
__global__ void wpack_log_k(const float* __restrict__ Wl, const float* __restrict__ lsc,
                            uint32_t* __restrict__ dst){
    __shared__ float red[8];
    int r = blockIdx.x;
    const float4* sp = (const float4*)(Wl + (size_t)r*Dm);
    float4 v = sp[threadIdx.x];
    float s = v.x*v.x + v.y*v.y + v.z*v.z + v.w*v.w;
    s = blocksum256(s, red);
    float f = l2fac(sqrtf(s))*lsc[r]*32.0f;
    dst[cidx(r, 2*threadIdx.x,   NCKD)] = packh2(v.x*f, v.y*f);
    dst[cidx(r, 2*threadIdx.x+1, NCKD)] = packh2(v.z*f, v.w*f);
}

// ---------------- embedding ----------------
__global__ void embed_k(const int* __restrict__ ids, const float* __restrict__ W_emb,
                        float* __restrict__ x, uint32_t* __restrict__ xp2){
    __shared__ float red[8];
    int m = blockIdx.x, t = threadIdx.x;
    int tok = ids[m];
    const float2* row2 = (const float2*)(W_emb + (size_t)tok*Dm);
    float2 a = row2[t], b = row2[t+256];
    float s = a.x*a.x + a.y*a.y + b.x*b.x + b.y*b.y;
    s = blocksum256(s, red);
    float f = l2fac(sqrtf(s));
    a.x*=f; a.y*=f; b.x*=f; b.y*=f;
    float2* x2 = (float2*)(x + (size_t)m*Dm);
    x2[t] = a; x2[t+256] = b;
    xp2[cidx(m, t,     NCKD)] = packh2(a.x, a.y);
    xp2[cidx(m, t+256, NCKD)] = packh2(b.x, b.y);
}

// ---------------- fused attn-prep + delta rule (256 threads, 4-way split, prefetch) ----------------
#define DCH 32
__global__ void __launch_bounds__(256)
delta_k(const float* __restrict__ qkv, const float* __restrict__ qs_l,
        const float* __restrict__ Wbeta, const float* __restrict__ bscale,
        int l, int is_l0, float* __restrict__ v0h,
        uint32_t* __restrict__ op2, const float* __restrict__ fWo){
    int bh = blockIdx.x;
    int b = bh / NH, h = bh % NH;
    int t = threadIdx.x;
    int warp = t>>5, lane = t&31;
    int col = t>>2, par = t&3;

    float wb0 = Wbeta[l*DHd + lane], wb1 = Wbeta[l*DHd + lane + 32];
    float wfac = l2fac(sqrtf(warpsum(wb0*wb0 + wb1*wb1))) * (bscale[l]*0.1f);
    float wbn0 = wb0*wfac, wbn1 = wb1*wfac;
    float qsc0 = qs_l[h*DHd + lane]*1024.0f, qsc1 = qs_l[h*DHd + lane + 32]*1024.0f;

    float St[16];
    #pragma unroll
    for(int i=0;i<16;i++) St[i] = 0.0f;

    __shared__ float ks[DCH*DHd];
    __shared__ float qs[DCH*DHd];
    __shared__ float vs[DCH*DHd];
    __shared__ float bs[DCH];

    float fo = fWo[h*DHd + col];

    // prefetch registers: 4 tokens per thread
    float rq0[4],rq1[4],rk0[4],rk1[4],rv0[4],rv1[4],rw0[4],rw1[4];
    #define LOADC(c0_) do{                                                   \
        _Pragma("unroll")                                                    \
        for(int j_=0;j_<4;j_++){                                             \
            int i_ = warp + 8*j_;                                            \
            int m_ = b*SEQn + (c0_) + i_;                                    \
            size_t src_ = (size_t)m_*NQKV + h*DHd;                           \
            rq0[j_]=qkv[src_+lane];        rq1[j_]=qkv[src_+lane+32];        \
            rk0[j_]=qkv[src_+Dm+lane];     rk1[j_]=qkv[src_+Dm+lane+32];     \
            rv0[j_]=qkv[src_+2*Dm+lane];   rv1[j_]=qkv[src_+2*Dm+lane+32];   \
            if(!is_l0){                                                      \
                size_t vd_ = ((size_t)bh*SEQn + (c0_) + i_)*DHd;             \
                rw0[j_]=v0h[vd_+lane];     rw1[j_]=v0h[vd_+lane+32];         \
            }                                                                \
        }                                                                    \
    }while(0)

    LOADC(0);

    for(int c0=0;c0<SEQn;c0+=DCH){
        // normalize + store from prefetched registers
        #pragma unroll
        for(int j=0;j<4;j++){
            int i = warp + 8*j;
            float q0=rq0[j], q1=rq1[j];
            float k0=rk0[j], k1=rk1[j];
            float v0=rv0[j], v1=rv1[j];
            float fq = l2fac(sqrtf(warpsum(q0*q0 + q1*q1)));
            float fk = l2fac(sqrtf(warpsum(k0*k0 + k1*k1)));
            float kn0 = k0*fk, kn1 = k1*fk;
            float bd = warpsum(kn0*wbn0 + kn1*wbn1);
            float vv0, vv1;
            if(is_l0){
                size_t vd = ((size_t)bh*SEQn + c0 + i)*DHd;
                vv0=v0; vv1=v1; v0h[vd+lane]=v0; v0h[vd+lane+32]=v1;
            } else {
                vv0=0.5f*(v0 + rw0[j]); vv1=0.5f*(v1 + rw1[j]);
            }
            qs[i*DHd+lane] = q0*fq*qsc0;  qs[i*DHd+lane+32] = q1*fq*qsc1;
            ks[i*DHd+lane] = kn0;         ks[i*DHd+lane+32] = kn1;
            vs[i*DHd+lane] = vv0;         vs[i*DHd+lane+32] = vv1;
            if(lane==0) bs[i] = 1.0f/(1.0f + __expf(-bd));
        }
        __syncthreads();
        // issue next chunk's global loads; latency hidden under recurrence
        if(c0 + DCH < SEQn) LOADC(c0 + DCH);

        for(int tt=0;tt<DCH;tt++){
            const float* kt = &ks[tt*DHd];
            const float* qt = &qs[tt*DHd];
            float p0=0,p1=0,p2=0,p3=0;
            #pragma unroll
            for(int j=0;j<16;j+=4){
                p0 += kt[4*j+par]*St[j];
                p1 += kt[4*(j+1)+par]*St[j+1];
                p2 += kt[4*(j+2)+par]*St[j+2];
                p3 += kt[4*(j+3)+par]*St[j+3];
            }
            float kS = (p0+p1)+(p2+p3);
            kS += __shfl_xor_sync(0xffffffffu, kS, 1);
            kS += __shfl_xor_sync(0xffffffffu, kS, 2);
            float dlt = bs[tt]*(vs[tt*DHd + col] - kS);
            float o0=0,o1=0,o2=0,o3=0;
            #pragma unroll
            for(int j=0;j<16;j+=4){
                St[j]   += kt[4*j+par]*dlt;     o0 += qt[4*j+par]*St[j];
                St[j+1] += kt[4*(j+1)+par]*dlt; o1 += qt[4*(j+1)+par]*St[j+1];
                St[j+2] += kt[4*(j+2)+par]*dlt; o2 += qt[4*(j+2)+par]*St[j+2];
                St[j+3] += kt[4*(j+3)+par]*dlt; o3 += qt[4*(j+3)+par]*St[j+3];
            }
            float o = (o0+o1)+(o2+o3);
            o += __shfl_xor_sync(0xffffffffu, o, 1);
            o += __shfl_xor_sync(0xffffffffu, o, 2);
            o *= fo;
            float oN = __shfl_down_sync(0xffffffffu, o, 4);
            if((t & 7) == 0){
                int m = b*SEQn + c0 + tt;
                op2[cidx(m, h*32 + (col>>1), NCKD)] = packh2(o, oN);
            }
        }
        __syncthreads();
    }
    #undef LOADC
}

// ---------------- residual ----------------
__global__ void resid_k(float* __restrict__ x, const float* __restrict__ o,
                        const float* __restrict__ alpha, uint32_t* __restrict__ xp2){
    __shared__ float red[8];
    int m = blockIdx.x, t = threadIdx.x;
    const float2* o2 = (const float2*)(o + (size_t)m*Dm);
    float2 oa = o2[t], ob = o2[t+256];
    float s = oa.x*oa.x + oa.y*oa.y + ob.x*ob.x + ob.y*ob.y;
    s = blocksum256(s, red);
    float fh = l2fac(sqrtf(s));
    float2* x2 = (float2*)(x + (size_t)m*Dm);
    float2 xa = x2[t], xb = x2[t+256];
    const float2* al2 = (const float2*)alpha;
    float2 aa = al2[t], ab = al2[t+256];
    float ya0 = xa.x + aa.x*8.0f*(oa.x*fh - xa.x);
    float ya1 = xa.y + aa.y*8.0f*(oa.y*fh - xa.y);
    float yb0 = xb.x + ab.x*8.0f*(ob.x*fh - xb.x);
    float yb1 = xb.y + ab.y*8.0f*(ob.y*fh - xb.y);
    float s2 = ya0*ya0 + ya1*ya1 + yb0*yb0 + yb1*yb1;
    s2 = blocksum256(s2, red);
    float f2 = l2fac(sqrtf(s2));
    ya0*=f2; ya1*=f2; yb0*=f2; yb1*=f2;
    x2[t]     = make_float2(ya0, ya1);
    x2[t+256] = make_float2(yb0, yb1);
    xp2[cidx(m, t,     NCKD)] = packh2(ya0, ya1);
    xp2[cidx(m, t+256, NCKD)] = packh2(yb0, yb1);
}

// ---------------- host ----------------
struct GraphAux {
    cudaStream_t s1;
    cudaEvent_t evRoot, evQ0, evCn1, evO, evQ, evHg, evFo, evLog;
    GraphAux(){
        cudaStreamCreateWithFlags(&s1, cudaStreamNonBlocking);
        cudaEventCreateWithFlags(&evRoot, cudaEventDisableTiming);
        cudaEventCreateWithFlags(&evQ0,   cudaEventDisableTiming);
        cudaEventCreateWithFlags(&evCn1,  cudaEventDisableTiming);
        cudaEventCreateWithFlags(&evO,    cudaEventDisableTiming);
        cudaEventCreateWithFlags(&evQ,    cudaEventDisableTiming);
        cudaEventCreateWithFlags(&evHg,   cudaEventDisableTiming);
        cudaEventCreateWithFlags(&evFo,   cudaEventDisableTiming);
        cudaEventCreateWithFlags(&evLog,  cudaEventDisableTiming);
    }
};
static GraphAux g_aux;

template<typename T> static void* symaddr(T& s){
    void* p = nullptr; cudaGetSymbolAddress(&p, s); return p;
}

extern "C" void kernel_launch(void* const* d_in, const int* in_sizes, int n_in,
                              void* d_out, int out_size){
    (void)in_sizes; (void)n_in; (void)out_size;
    const int*   ids        = (const int*)  d_in[0];
    const float* W_emb      = (const float*)d_in[2];
    const float* Wq         = (const float*)d_in[3];
    const float* Wk         = (const float*)d_in[4];
    const float* Wv         = (const float*)d_in[5];
    const float* Wbeta      = (const float*)d_in[6];
    const float* Wo         = (const float*)d_in[7];
    const float* Wffh       = (const float*)d_in[8];
    const float* Wffg       = (const float*)d_in[9];
    const float* Wffo       = (const float*)d_in[10];
    const float* qk_scale   = (const float*)d_in[11];
    const float* beta_scale = (const float*)d_in[12];
    const float* attn_alpha = (const float*)d_in[13];
    const float* ff_alpha   = (const float*)d_in[14];
    const float* ffh_scale  = (const float*)d_in[15];
    const float* ffg_scale  = (const float*)d_in[16];
    const float* W_logits   = (const float*)d_in[17];
    const float* logit_scale= (const float*)d_in[18];
    float* out = (float*)d_out;

    float* x     = (float*)symaddr(g_x);
    float* qkv   = (float*)symaddr(g_qkv);
    float* obuf  = (float*)symaddr(g_obuf);
    float* v0h   = (float*)symaddr(g_v0h);
    float* fo    = (float*)symaddr(g_fo);
    float* fffo  = (float*)symaddr(g_fffo);
    float* part  = (float*)symaddr(g_part);
    uint32_t* xp2   = (uint32_t*)symaddr(g_xp2);
    uint32_t* op2   = (uint32_t*)symaddr(g_op2);
    uint32_t* zp2   = (uint32_t*)symaddr(g_zp2);
    uint32_t* wqkv2 = (uint32_t*)symaddr(g_wqkv2);
    uint32_t* wo2   = (uint32_t*)symaddr(g_wo2);
    uint32_t* whg2  = (uint32_t*)symaddr(g_whg2);
    uint32_t* wfo2  = (uint32_t*)symaddr(g_wfo2);
    uint32_t* wl2   = (uint32_t*)symaddr(g_wl2);

    cudaFuncSetAttribute(gemm_mma_k<128,128,64,32,3,0>, cudaFuncAttributeMaxDynamicSharedMemorySize, 99328);
    cudaFuncSetAttribute(gemm_hg_k<128,64,32,32,3>,     cudaFuncAttributeMaxDynamicSharedMemorySize, 74752);
    cudaFuncSetAttribute(gemm_mma_k<64,64,32,16,4,0>,   cudaFuncAttributeMaxDynamicSharedMemorySize, 66560);

    cudaStream_t s1 = g_aux.s1;

    cudaEventRecord(g_aux.evRoot, 0);
    cudaStreamWaitEvent(s1, g_aux.evRoot, 0);

    // side stream: earliest-consumer order; layer-0 qkv pack first
    wpack_qkv_k<<<NQKV, 256, 0, s1>>>(Wq, Wk, Wv, 0, wqkv2);
    cudaEventRecord(g_aux.evQ0, s1);
    colnorm_part_k<<<dim3(Dm/256, NL, 8), 256, 0, s1>>>(Wo, part, Dm, Dm);
    colnorm_fin_k<<<dim3(Dm/256, NL), 256, 0, s1>>>(part, fo, Dm);
    cudaEventRecord(g_aux.evCn1, s1);
    wpack_o_k<<<NL*Dm, 256, 0, s1>>>(Wo, wo2);
    cudaEventRecord(g_aux.evO, s1);
    wpack_hg_k<<<NL*NHG, 256, 0, s1>>>(Wffh, Wffg, ffh_scale, ffg_scale, whg2);
    cudaEventRecord(g_aux.evHg, s1);
    wpack_qkv_k<<<3*NQKV, 256, 0, s1>>>(Wq, Wk, Wv, 1, wqkv2);
    cudaEventRecord(g_aux.evQ, s1);
    colnorm_part_k<<<dim3((DFFn+255)/256, NL, 8), 256, 0, s1>>>(Wffo, part, Dm, DFFn);
    colnorm_fin_k<<<dim3((DFFn+255)/256, NL), 256, 0, s1>>>(part, fffo, DFFn);
    wpack_fo_k<<<NL*Dm, 256, 0, s1>>>(Wffo, fffo, wfo2);
    cudaEventRecord(g_aux.evFo, s1);
    wpack_log_k<<<NV, 256, 0, s1>>>(W_logits, logit_scale, wl2);
    cudaEventRecord(g_aux.evLog, s1);

    // main stream
    embed_k<<<MT, 256>>>(ids, W_emb, x, xp2);

    for(int l=0;l<NL;l++){
        if(l==0) cudaStreamWaitEvent(0, g_aux.evQ0, 0);
        if(l==1) cudaStreamWaitEvent(0, g_aux.evQ, 0);
        gemm_mma_k<128,128,64,32,3,0><<<dim3(8, NQKV/128), 256, 99328>>>(
            xp2, wqkv2 + (size_t)l*NQKV*UD, qkv, NQKV, Dm);
        if(l==0) cudaStreamWaitEvent(0, g_aux.evCn1, 0);
        delta_k<<<NB*NH, 256>>>(qkv, qk_scale + l*Dm, Wbeta, beta_scale, l,
                                (l==0)?1:0, v0h, op2, fo + l*Dm);
        if(l==0) cudaStreamWaitEvent(0, g_aux.evO, 0);
        gemm_mma_k<64,64,32,16,4,0><<<dim3(16, 16), 256, 66560>>>(
            op2, wo2 + (size_t)l*Dm*UD, obuf, Dm, Dm);
        resid_k<<<MT, 256>>>(x, obuf, attn_alpha + l*Dm, xp2);
        if(l==0) cudaStreamWaitEvent(0, g_aux.evHg, 0);
        gemm_hg_k<128,64,32,32,3><<<dim3(8, NHG/64), 256, 74752>>>(
            xp2, whg2 + (size_t)l*NHG*UD, zp2, NCKF, Dm);
        if(l==0) cudaStreamWaitEvent(0, g_aux.evFo, 0);
        gemm_mma_k<64,64,32,16,4,0><<<dim3(16, 16), 256, 66560>>>(
            zp2, wfo2 + (size_t)l*Dm*UF, obuf, Dm, DFFP);
        resid_k<<<MT, 256>>>(x, obuf, ff_alpha + l*Dm, xp2);
    }
    cudaStreamWaitEvent(0, g_aux.evLog, 0);
    gemm_mma_k<128,128,64,32,3,0><<<dim3(8, NV/128), 256, 99328>>>(
        xp2, wl2, out, NV, Dm);
}

// round 17
// speedup vs baseline: 1.2644x; 1.0105x over previous
#include <cuda_runtime.h>
#include <cuda_bf16.h>
#include <cuda_fp16.h>
#include <math.h>
#include <stdint.h>

#define Dm    1024
#define SEQn  512
#define NB    2
#define NH    16
#define DHd   64
#define DFFn  2730
#define DFFP  2816
#define NV    32000
#define NL    4
#define MT    1024
#define NQKV  3072
#define NHG   5632
#define UD    512
#define UF    1408
#define NCKD  16
#define NCKF  44

#define GDC_WAIT()   asm volatile("griddepcontrol.wait;" ::: "memory")
#define GDC_LAUNCH() asm volatile("griddepcontrol.launch_dependents;" ::: "memory")

// ---------------- fp32 scratch ----------------
__device__ float g_x[MT*Dm];
__device__ float g_qkv[MT*NQKV];
__device__ float g_obuf[MT*Dm];
__device__ float g_v0h[NB*NH*SEQn*DHd];
__device__ float g_fo[NL*Dm];
__device__ float g_fffo[NL*DFFn];
__device__ float g_part[8*NL*DFFP];

// ---------------- packed fp16 buffers, chunked pre-swizzled layout ----------------
__device__ uint32_t g_xp2 [MT*UD];
__device__ uint32_t g_op2 [MT*UD];
__device__ uint32_t g_zp2 [MT*UF];
__device__ uint32_t g_wqkv2[(size_t)NL*NQKV*UD];
__device__ uint32_t g_wo2  [(size_t)NL*Dm*UD];
__device__ uint32_t g_whg2 [(size_t)NL*NHG*UD];
__device__ uint32_t g_wfo2 [(size_t)NL*Dm*UF];
__device__ uint32_t g_wl2  [(size_t)NV*UD];

static __device__ __forceinline__ size_t cidx(int gr, int j, int ncK){
    return ((size_t)(gr>>7)*ncK + (j>>5))*4096 + (size_t)(gr&127)*32
         + ((((j>>2)&7) ^ (gr&7))<<2) + (j&3);
}

// ---------------- scalar helpers ----------------
static __device__ __forceinline__ float l2fac(float n){
    float tgt = fminf(fmaxf(n, 1.0f - 1e-5f), 1.0f + 1e-5f);
    return 1.0f / fmaxf(n / tgt, 1e-10f);
}
static __device__ __forceinline__ float warpsum(float v){
    #pragma unroll
    for(int o=16;o>0;o>>=1) v += __shfl_xor_sync(0xffffffffu, v, o);
    return v;
}
static __device__ __forceinline__ float blocksum256(float v, float* red){
    v = warpsum(v);
    if((threadIdx.x&31)==0) red[threadIdx.x>>5] = v;
    __syncthreads();
    float s = ((red[0]+red[1])+(red[2]+red[3])) + ((red[4]+red[5])+(red[6]+red[7]));
    __syncthreads();
    return s;
}
static __device__ __forceinline__ uint32_t packh2(float x0, float x1){
    return (uint32_t)__half_as_ushort(__float2half_rn(x0))
         | ((uint32_t)__half_as_ushort(__float2half_rn(x1))<<16);
}

// ---------------- bulk-copy / mbarrier / ldmatrix / mma primitives ----------------
static __device__ __forceinline__ void mbar_init(uint32_t a, uint32_t c){
    asm volatile("mbarrier.init.shared.b64 [%0], %1;" :: "r"(a), "r"(c) : "memory");
}
static __device__ __forceinline__ void mbar_expect(uint32_t a, uint32_t bytes){
    asm volatile("mbarrier.arrive.expect_tx.shared.b64 _, [%0], %1;"
                 :: "r"(a), "r"(bytes) : "memory");
}
static __device__ __forceinline__ void mbar_wait(uint32_t a, uint32_t ph){
    asm volatile("{\n\t.reg .pred P;\n\t"
        "WL_%=:\n\t"
        "mbarrier.try_wait.parity.shared.b64 P, [%0], %1;\n\t"
        "@P bra.uni WD_%=;\n\t"
        "bra.uni WL_%=;\n\t"
        "WD_%=:\n\t}"
        :: "r"(a), "r"(ph) : "memory");
}
static __device__ __forceinline__ void bulkcp(uint32_t dst, const void* src, uint32_t bytes,
                                              uint32_t mbar){
    asm volatile("cp.async.bulk.shared::cluster.global.mbarrier::complete_tx::bytes "
                 "[%0], [%1], %2, [%3];"
                 :: "r"(dst), "l"(src), "r"(bytes), "r"(mbar) : "memory");
}
static __device__ __forceinline__ void ldsm4(uint32_t* r, uint32_t a){
    asm volatile("ldmatrix.sync.aligned.m8n8.x4.shared.b16 {%0,%1,%2,%3}, [%4];"
        : "=r"(r[0]),"=r"(r[1]),"=r"(r[2]),"=r"(r[3]) : "r"(a));
}
static __device__ __forceinline__ void mma_f16(float* c,
        uint32_t a0, uint32_t a1, uint32_t a2, uint32_t a3, uint32_t b0, uint32_t b1){
    asm volatile("mma.sync.aligned.m16n8k16.row.col.f32.f16.f16.f32 "
                 "{%0,%1,%2,%3},{%4,%5,%6,%7},{%8,%9},{%0,%1,%2,%3};"
                 : "+f"(c[0]), "+f"(c[1]), "+f"(c[2]), "+f"(c[3])
                 : "r"(a0), "r"(a1), "r"(a2), "r"(a3), "r"(b0), "r"(b1));
}

// ---------------- bulk-copy mma GEMM: C[M,N] = A @ B^T (fp32 out) ----------------
template<int BM,int BN,int WM,int WN,int S,int EPI>
__global__ void __launch_bounds__(256, 2)
gemm_mma_k(const uint32_t* __restrict__ Au, const uint32_t* __restrict__ Bu,
           void* __restrict__ Cv, int ldc, int Ks){
    constexpr int ABYTES = BM*128, BBYTES = BN*128, STAGE = ABYTES+BBYTES;
    constexpr int WNW = BN/WN;
    constexpr int MI = WM/16, NJ = WN/8, NJ2 = NJ/2;

    extern __shared__ char sm[];
    uint32_t smBase = (uint32_t)__cvta_generic_to_shared(sm);
    uint32_t mb = smBase;
    uint32_t tiles = smBase + 1024;

    const int tid = threadIdx.x, warp = tid>>5, lane = tid&31;
    const int wm = warp / WNW, wn = warp % WNW;
    const int i8 = lane&7, sub = lane>>3;
    const int g = lane>>2, t4 = lane&3;
    const int rowBase = blockIdx.x*BM, colBase = blockIdx.y*BN;
    const int NC = Ks>>6;

    const char* AbBase = (const char*)Au + ((size_t)(rowBase>>7)*NC)*16384
                       + (size_t)((rowBase>>6)&1)*8192;
    const char* BbBase = (const char*)Bu + ((size_t)(colBase>>7)*NC)*16384
                       + (size_t)((colBase>>6)&1)*8192;

    if(tid==0){
        #pragma unroll
        for(int s=0;s<S;s++) mbar_init(mb + 8*s, 1);
    }
    __syncthreads();
    GDC_WAIT();
    if(tid==0){
        #pragma unroll
        for(int s=0;s<S-1;s++){
            mbar_expect(mb + 8*s, STAGE);
            bulkcp(tiles + s*STAGE,          AbBase + (size_t)s*16384, ABYTES, mb + 8*s);
            bulkcp(tiles + s*STAGE + ABYTES, BbBase + (size_t)s*16384, BBYTES, mb + 8*s);
        }
    }

    const int cA = sub>>1, cB = sub&1;
    uint32_t aRow[MI], bRow[NJ2];
    #pragma unroll
    for(int it=0;it<MI;it++)
        aRow[it] = tiles + (uint32_t)((wm*WM + it*16 + (sub&1)*8 + i8)*128);
    #pragma unroll
    for(int jp=0;jp<NJ2;jp++)
        bRow[jp] = tiles + (uint32_t)(ABYTES + (wn*WN + jp*16 + (sub>>1)*8 + i8)*128);

    float acc[MI][NJ][4];
    #pragma unroll
    for(int i=0;i<MI;i++)
        #pragma unroll
        for(int j=0;j<NJ;j++)
            #pragma unroll
            for(int e=0;e<4;e++) acc[i][j][e] = 0.0f;

    uint32_t ahB[2][MI][4], bbB[2][NJ2][4];

    for(int c=0;c<NC;c++){
        int s = c % S;
        mbar_wait(mb + 8*s, (uint32_t)((c/S)&1));
        if(tid==0 && c+S-1 < NC){
            int s2 = (c+S-1)%S;
            mbar_expect(mb + 8*s2, STAGE);
            bulkcp(tiles + s2*STAGE,          AbBase + (size_t)(c+S-1)*16384, ABYTES, mb + 8*s2);
            bulkcp(tiles + s2*STAGE + ABYTES, BbBase + (size_t)(c+S-1)*16384, BBYTES, mb + 8*s2);
        }
        const uint32_t bufOff = (uint32_t)(s*STAGE);

        #define LD_FRAG(kk, p) do{                                                   \
            _Pragma("unroll")                                                        \
            for(int it_=0;it_<MI;it_++)                                              \
                ldsm4(ahB[p][it_], aRow[it_] + bufOff + (uint32_t)((((2*(kk) + cA) ^ i8))<<4)); \
            _Pragma("unroll")                                                        \
            for(int jp_=0;jp_<NJ2;jp_++)                                             \
                ldsm4(bbB[p][jp_], bRow[jp_] + bufOff + (uint32_t)((((2*(kk) + cB) ^ i8))<<4)); \
        }while(0)

        LD_FRAG(0, 0);
        #pragma unroll
        for(int kk=0;kk<4;kk++){
            const int cur = kk&1;
            if(kk<3) LD_FRAG(kk+1, cur^1);
            #pragma unroll
            for(int it=0;it<MI;it++)
                #pragma unroll
                for(int jt=0;jt<NJ;jt++){
                    const uint32_t* bf = bbB[cur][jt>>1];
                    int o = (jt&1)*2;
                    mma_f16(acc[it][jt], ahB[cur][it][0], ahB[cur][it][1],
                            ahB[cur][it][2], ahB[cur][it][3], bf[o], bf[o+1]);
                }
        }
        #undef LD_FRAG
        __syncthreads();
    }

    float* C = (float*)Cv;
    #pragma unroll
    for(int jt=0;jt<NJ;jt++){
        int c = colBase + wn*WN + jt*8 + t4*2;
        #pragma unroll
        for(int it=0;it<MI;it++){
            int r = rowBase + wm*WM + it*16 + g;
            *(float2*)(C + (size_t)r*ldc + c)     = make_float2(acc[it][jt][0], acc[it][jt][1]);
            *(float2*)(C + (size_t)(r+8)*ldc + c) = make_float2(acc[it][jt][2], acc[it][jt][3]);
        }
    }
    GDC_LAUNCH();   // after all stores: release-visible to dependents
}

// hg GEMM: (h,g) col pairs -> packed fp16 silu(g)*h into chunked C
template<int BM,int BN,int WM,int WN,int S>
__global__ void __launch_bounds__(256, 2)
gemm_hg_k(const uint32_t* __restrict__ Au, const uint32_t* __restrict__ Bu,
          uint32_t* __restrict__ Cv, int ncK, int Ks){
    constexpr int ABYTES = BM*128, BBYTES = BN*128, STAGE = ABYTES+BBYTES;
    constexpr int WNW = BN/WN;
    constexpr int MI = WM/16, NJ = WN/8, NJ2 = NJ/2;

    extern __shared__ char sm[];
    uint32_t smBase = (uint32_t)__cvta_generic_to_shared(sm);
    uint32_t mb = smBase;
    uint32_t tiles = smBase + 1024;

    const int tid = threadIdx.x, warp = tid>>5, lane = tid&31;
    const int wm = warp / WNW, wn = warp % WNW;
    const int i8 = lane&7, sub = lane>>3;
    const int g = lane>>2, t4 = lane&3;
    const int rowBase = blockIdx.x*BM, colBase = blockIdx.y*BN;
    const int NC = Ks>>6;

    const char* AbBase = (const char*)Au + ((size_t)(rowBase>>7)*NC)*16384
                       + (size_t)((rowBase>>6)&1)*8192;
    const char* BbBase = (const char*)Bu + ((size_t)(colBase>>7)*NC)*16384
                       + (size_t)((colBase>>6)&1)*8192;

    if(tid==0){
        #pragma unroll
        for(int s=0;s<S;s++) mbar_init(mb + 8*s, 1);
    }
    __syncthreads();
    GDC_WAIT();
    if(tid==0){
        #pragma unroll
        for(int s=0;s<S-1;s++){
            mbar_expect(mb + 8*s, STAGE);
            bulkcp(tiles + s*STAGE,          AbBase + (size_t)s*16384, ABYTES, mb + 8*s);
            bulkcp(tiles + s*STAGE + ABYTES, BbBase + (size_t)s*16384, BBYTES, mb + 8*s);
        }
    }

    const int cA = sub>>1, cB = sub&1;
    uint32_t aRow[MI], bRow[NJ2];
    #pragma unroll
    for(int it=0;it<MI;it++)
        aRow[it] = tiles + (uint32_t)((wm*WM + it*16 + (sub&1)*8 + i8)*128);
    #pragma unroll
    for(int jp=0;jp<NJ2;jp++)
        bRow[jp] = tiles + (uint32_t)(ABYTES + (wn*WN + jp*16 + (sub>>1)*8 + i8)*128);

    float acc[MI][NJ][4];
    #pragma unroll
    for(int i=0;i<MI;i++)
        #pragma unroll
        for(int j=0;j<NJ;j++)
            #pragma unroll
            for(int e=0;e<4;e++) acc[i][j][e] = 0.0f;

    uint32_t ahB[2][MI][4], bbB[2][NJ2][4];

    for(int c=0;c<NC;c++){
        int s = c % S;
        mbar_wait(mb + 8*s, (uint32_t)((c/S)&1));
        if(tid==0 && c+S-1 < NC){
            int s2 = (c+S-1)%S;
            mbar_expect(mb + 8*s2, STAGE);
            bulkcp(tiles + s2*STAGE,          AbBase + (size_t)(c+S-1)*16384, ABYTES, mb + 8*s2);
            bulkcp(tiles + s2*STAGE + ABYTES, BbBase + (size_t)(c+S-1)*16384, BBYTES, mb + 8*s2);
        }
        const uint32_t bufOff = (uint32_t)(s*STAGE);

        #define LD_FRAG(kk, p) do{                                                   \
            _Pragma("unroll")                                                        \
            for(int it_=0;it_<MI;it_++)                                              \
                ldsm4(ahB[p][it_], aRow[it_] + bufOff + (uint32_t)((((2*(kk) + cA) ^ i8))<<4)); \
            _Pragma("unroll")                                                        \
            for(int jp_=0;jp_<NJ2;jp_++)                                             \
                ldsm4(bbB[p][jp_], bRow[jp_] + bufOff + (uint32_t)((((2*(kk) + cB) ^ i8))<<4)); \
        }while(0)

        LD_FRAG(0, 0);
        #pragma unroll
        for(int kk=0;kk<4;kk++){
            const int cur = kk&1;
            if(kk<3) LD_FRAG(kk+1, cur^1);
            #pragma unroll
            for(int it=0;it<MI;it++)
                #pragma unroll
                for(int jt=0;jt<NJ;jt++){
                    const uint32_t* bf = bbB[cur][jt>>1];
                    int o = (jt&1)*2;
                    mma_f16(acc[it][jt], ahB[cur][it][0], ahB[cur][it][1],
                            ahB[cur][it][2], ahB[cur][it][3], bf[o], bf[o+1]);
                }
        }
        #undef LD_FRAG
        __syncthreads();
    }

    #pragma unroll
    for(int jt=0;jt<NJ;jt++){
        int i0 = ((colBase + wn*WN + jt*8)>>1) + t4;
        #pragma unroll
        for(int it=0;it<MI;it++){
            int r = rowBase + wm*WM + it*16 + g;
            float h0 = acc[it][jt][0], g0 = acc[it][jt][1];
            float h1 = acc[it][jt][2], g1 = acc[it][jt][3];
            float z0 = g0/(1.0f + __expf(-g0))*h0;
            float z1 = g1/(1.0f + __expf(-g1))*h1;
            float z0n = __shfl_xor_sync(0xffffffffu, z0, 1);
            float z1n = __shfl_xor_sync(0xffffffffu, z1, 1);
            if((t4 & 1) == 0){
                int j = i0>>1;
                Cv[cidx(r,   j, ncK)] = packh2(z0, z0n);
                Cv[cidx(r+8, j, ncK)] = packh2(z1, z1n);
            }
        }
    }
    GDC_LAUNCH();
}

// ---------------- split column norms: 8-way row partials + finalize ----------------
__global__ void colnorm_part_k(const float* __restrict__ W, float* __restrict__ part,
                               int R, int C){
    int l = blockIdx.y;
    int c = blockIdx.x*256 + threadIdx.x;
    int sp = blockIdx.z;
    if(c >= C) return;
    const float* Wl = W + (size_t)l*R*C;
    int r0 = sp*(R>>3), r1 = r0 + (R>>3);
    float s = 0.0f;
    for(int r=r0;r<r1;r++){ float w = Wl[(size_t)r*C + c]; s += w*w; }
    part[((size_t)sp*NL + l)*DFFP + c] = s;
}
__global__ void colnorm_fin_k(const float* __restrict__ part, float* __restrict__ f, int C){
    int l = blockIdx.y;
    int c = blockIdx.x*256 + threadIdx.x;
    if(c >= C) return;
    float s = 0.0f;
    #pragma unroll
    for(int sp=0;sp<8;sp++) s += part[((size_t)sp*NL + l)*DFFP + c];
    f[(size_t)l*C + c] = l2fac(sqrtf(s));
}

// ---------------- fused norm + pack kernels ----------------
__global__ void wpack_qkv_k(const float* __restrict__ Wq, const float* __restrict__ Wk,
                            const float* __restrict__ Wv, int lbase,
                            uint32_t* __restrict__ dst){
    __shared__ float red[8];
    int rr = blockIdx.x + lbase*NQKV;
    int l = rr / NQKV, r = rr % NQKV;
    int which = r >> 10, rl = r & 1023;
    const float* W = (which==0) ? Wq : (which==1) ? Wk : Wv;
    const float4* sp = (const float4*)(W + ((size_t)l*Dm + rl)*Dm);
    float4 v = sp[threadIdx.x];
    float s = v.x*v.x + v.y*v.y + v.z*v.z + v.w*v.w;
    s = blocksum256(s, red);
    float f = l2fac(sqrtf(s));
    dst[cidx(rr, 2*threadIdx.x,   NCKD)] = packh2(v.x*f, v.y*f);
    dst[cidx(rr, 2*threadIdx.x+1, NCKD)] = packh2(v.z*f, v.w*f);
}
__global__ void wpack_o_k(const float* __restrict__ Wo, uint32_t* __restrict__ dst){
    int rr = blockIdx.x;
    const float4* sp = (const float4*)(Wo + (size_t)rr*Dm);
    float4 v = sp[threadIdx.x];
    dst[cidx(rr, 2*threadIdx.x,   NCKD)] = packh2(v.x, v.y);
    dst[cidx(rr, 2*threadIdx.x+1, NCKD)] = packh2(v.z, v.w);
}
__global__ void wpack_hg_k(const float* __restrict__ Wffh, const float* __restrict__ Wffg,
                           const float* __restrict__ hsc, const float* __restrict__ gsc,
                           uint32_t* __restrict__ dst){
    __shared__ float red[8];
    int rr = blockIdx.x;
    int l = rr / NHG, r = rr % NHG;
    int p = r >> 1, isG = r & 1;
    if(p >= DFFn){
        dst[cidx(rr, 2*threadIdx.x,   NCKD)] = 0u;
        dst[cidx(rr, 2*threadIdx.x+1, NCKD)] = 0u;
        return;
    }
    size_t sr = (size_t)l*DFFn + p;
    const float* W = isG ? (Wffg + sr*Dm) : (Wffh + sr*Dm);
    float sc = isG ? gsc[sr]*32.0f : hsc[sr];
    float4 v = ((const float4*)W)[threadIdx.x];
    float s = v.x*v.x + v.y*v.y + v.z*v.z + v.w*v.w;
    s = blocksum256(s, red);
    float f = l2fac(sqrtf(s))*sc;
    dst[cidx(rr, 2*threadIdx.x,   NCKD)] = packh2(v.x*f, v.y*f);
    dst[cidx(rr, 2*threadIdx.x+1, NCKD)] = packh2(v.z*f, v.w*f);
}
__global__ void wpack_fo_k(const float* __restrict__ Wffo, const float* __restrict__ fffo,
                           uint32_t* __restrict__ dst){
    int rr = blockIdx.x;
    int l = rr / Dm, rl = rr % Dm;
    const float2* sp = (const float2*)(Wffo + ((size_t)l*Dm + rl)*DFFn);
    const float* ks = fffo + (size_t)l*DFFn;
    for(int j=threadIdx.x;j<UF;j+=256){
        float x0=0.0f, x1=0.0f;
        if(2*j < DFFn){ float2 vv = sp[j]; x0 = vv.x*ks[2*j]; x1 = vv.y*ks[2*j+1]; }
        dst[cidx(rr, j, NCKF)] = packh2(x0, x1);
    }
}
__global__ void wpack_log_k(const float* __restrict__ Wl, const float* __restrict__ lsc,
                            uint32_t* __restrict__ dst){
    __shared__ float red[8];
    int r = blockIdx.x;
    const float4* sp = (const float4*)(Wl + (size_t)r*Dm);
    float4 v = sp[threadIdx.x];
    float s = v.x*v.x + v.y*v.y + v.z*v.z + v.w*v.w;
    s = blocksum256(s, red);
    float f = l2fac(sqrtf(s))*lsc[r]*32.0f;
    dst[cidx(r, 2*threadIdx.x,   NCKD)] = packh2(v.x*f, v.y*f);
    dst[cidx(r, 2*threadIdx.x+1, NCKD)] = packh2(v.z*f, v.w*f);
}

// ---------------- embedding ----------------
__global__ void embed_k(const int* __restrict__ ids, const float* __restrict__ W_emb,
                        float* __restrict__ x, uint32_t* __restrict__ xp2){
    __shared__ float red[8];
    int m = blockIdx.x, t = threadIdx.x;
    int tok = ids[m];
    const float2* row2 = (const float2*)(W_emb + (size_t)tok*Dm);
    float2 a = row2[t], b = row2[t+256];
    float s = a.x*a.x + a.y*a.y + b.x*b.x + b.y*b.y;
    s = blocksum256(s, red);
    float f = l2fac(sqrtf(s));
    a.x*=f; a.y*=f; b.x*=f; b.y*=f;
    float2* x2 = (float2*)(x + (size_t)m*Dm);
    x2[t] = a; x2[t+256] = b;
    xp2[cidx(m, t,     NCKD)] = packh2(a.x, a.y);
    xp2[cidx(m, t+256, NCKD)] = packh2(b.x, b.y);
    GDC_LAUNCH();
}

// ---------------- fused attn-prep + delta rule (256 threads, 4-way split, prefetch) ----------------
#define DCH 32
__global__ void __launch_bounds__(256)
delta_k(const float* __restrict__ qkv, const float* __restrict__ qs_l,
        const float* __restrict__ Wbeta, const float* __restrict__ bscale,
        int l, int is_l0, float* __restrict__ v0h,
        uint32_t* __restrict__ op2, const float* __restrict__ fWo){
    int bh = blockIdx.x;
    int b = bh / NH, h = bh % NH;
    int t = threadIdx.x;
    int warp = t>>5, lane = t&31;
    int col = t>>2, par = t&3;

    GDC_WAIT();

    float wb0 = Wbeta[l*DHd + lane], wb1 = Wbeta[l*DHd + lane + 32];
    float wfac = l2fac(sqrtf(warpsum(wb0*wb0 + wb1*wb1))) * (bscale[l]*0.1f);
    float wbn0 = wb0*wfac, wbn1 = wb1*wfac;
    float qsc0 = qs_l[h*DHd + lane]*1024.0f, qsc1 = qs_l[h*DHd + lane + 32]*1024.0f;

    float St[16];
    #pragma unroll
    for(int i=0;i<16;i++) St[i] = 0.0f;

    __shared__ float ks[DCH*DHd];
    __shared__ float qs[DCH*DHd];
    __shared__ float vs[DCH*DHd];
    __shared__ float bs[DCH];

    float fo = fWo[h*DHd + col];

    float rq0[4],rq1[4],rk0[4],rk1[4],rv0[4],rv1[4],rw0[4],rw1[4];
    #define LOADC(c0_) do{                                                   \
        _Pragma("unroll")                                                    \
        for(int j_=0;j_<4;j_++){                                             \
            int i_ = warp + 8*j_;                                            \
            int m_ = b*SEQn + (c0_) + i_;                                    \
            size_t src_ = (size_t)m_*NQKV + h*DHd;                           \
            rq0[j_]=qkv[src_+lane];        rq1[j_]=qkv[src_+lane+32];        \
            rk0[j_]=qkv[src_+Dm+lane];     rk1[j_]=qkv[src_+Dm+lane+32];     \
            rv0[j_]=qkv[src_+2*Dm+lane];   rv1[j_]=qkv[src_+2*Dm+lane+32];   \
            if(!is_l0){                                                      \
                size_t vd_ = ((size_t)bh*SEQn + (c0_) + i_)*DHd;             \
                rw0[j_]=v0h[vd_+lane];     rw1[j_]=v0h[vd_+lane+32];         \
            }                                                                \
        }                                                                    \
    }while(0)

    LOADC(0);

    for(int c0=0;c0<SEQn;c0+=DCH){
        #pragma unroll
        for(int j=0;j<4;j++){
            int i = warp + 8*j;
            float q0=rq0[j], q1=rq1[j];
            float k0=rk0[j], k1=rk1[j];
            float v0=rv0[j], v1=rv1[j];
            float fq = l2fac(sqrtf(warpsum(q0*q0 + q1*q1)));
            float fk = l2fac(sqrtf(warpsum(k0*k0 + k1*k1)));
            float kn0 = k0*fk, kn1 = k1*fk;
            float bd = warpsum(kn0*wbn0 + kn1*wbn1);
            float vv0, vv1;
            if(is_l0){
                size_t vd = ((size_t)bh*SEQn + c0 + i)*DHd;
                vv0=v0; vv1=v1; v0h[vd+lane]=v0; v0h[vd+lane+32]=v1;
            } else {
                vv0=0.5f*(v0 + rw0[j]); vv1=0.5f*(v1 + rw1[j]);
            }
            qs[i*DHd+lane] = q0*fq*qsc0;  qs[i*DHd+lane+32] = q1*fq*qsc1;
            ks[i*DHd+lane] = kn0;         ks[i*DHd+lane+32] = kn1;
            vs[i*DHd+lane] = vv0;         vs[i*DHd+lane+32] = vv1;
            if(lane==0) bs[i] = 1.0f/(1.0f + __expf(-bd));
        }
        __syncthreads();
        if(c0 + DCH < SEQn) LOADC(c0 + DCH);

        for(int tt=0;tt<DCH;tt++){
            const float* kt = &ks[tt*DHd];
            const float* qt = &qs[tt*DHd];
            float p0=0,p1=0,p2=0,p3=0;
            #pragma unroll
            for(int j=0;j<16;j+=4){
                p0 += kt[4*j+par]*St[j];
                p1 += kt[4*(j+1)+par]*St[j+1];
                p2 += kt[4*(j+2)+par]*St[j+2];
                p3 += kt[4*(j+3)+par]*St[j+3];
            }
            float kS = (p0+p1)+(p2+p3);
            kS += __shfl_xor_sync(0xffffffffu, kS, 1);
            kS += __shfl_xor_sync(0xffffffffu, kS, 2);
            float dlt = bs[tt]*(vs[tt*DHd + col] - kS);
            float o0=0,o1=0,o2=0,o3=0;
            #pragma unroll
            for(int j=0;j<16;j+=4){
                St[j]   += kt[4*j+par]*dlt;     o0 += qt[4*j+par]*St[j];
                St[j+1] += kt[4*(j+1)+par]*dlt; o1 += qt[4*(j+1)+par]*St[j+1];
                St[j+2] += kt[4*(j+2)+par]*dlt; o2 += qt[4*(j+2)+par]*St[j+2];
                St[j+3] += kt[4*(j+3)+par]*dlt; o3 += qt[4*(j+3)+par]*St[j+3];
            }
            float o = (o0+o1)+(o2+o3);
            o += __shfl_xor_sync(0xffffffffu, o, 1);
            o += __shfl_xor_sync(0xffffffffu, o, 2);
            o *= fo;
            float oN = __shfl_down_sync(0xffffffffu, o, 4);
            if((t & 7) == 0){
                int m = b*SEQn + c0 + tt;
                op2[cidx(m, h*32 + (col>>1), NCKD)] = packh2(o, oN);
            }
        }
        __syncthreads();
    }
    #undef LOADC
    GDC_LAUNCH();
}

// ---------------- residual ----------------
__global__ void resid_k(float* __restrict__ x, const float* __restrict__ o,
                        const float* __restrict__ alpha, uint32_t* __restrict__ xp2){
    __shared__ float red[8];
    int m = blockIdx.x, t = threadIdx.x;
    GDC_WAIT();
    const float2* o2 = (const float2*)(o + (size_t)m*Dm);
    float2 oa = o2[t], ob = o2[t+256];
    float s = oa.x*oa.x + oa.y*oa.y + ob.x*ob.x + ob.y*ob.y;
    s = blocksum256(s, red);
    float fh = l2fac(sqrtf(s));
    float2* x2 = (float2*)(x + (size_t)m*Dm);
    float2 xa = x2[t], xb = x2[t+256];
    const float2* al2 = (const float2*)alpha;
    float2 aa = al2[t], ab = al2[t+256];
    float ya0 = xa.x + aa.x*8.0f*(oa.x*fh - xa.x);
    float ya1 = xa.y + aa.y*8.0f*(oa.y*fh - xa.y);
    float yb0 = xb.x + ab.x*8.0f*(ob.x*fh - xb.x);
    float yb1 = xb.y + ab.y*8.0f*(ob.y*fh - xb.y);
    float s2 = ya0*ya0 + ya1*ya1 + yb0*yb0 + yb1*yb1;
    s2 = blocksum256(s2, red);
    float f2 = l2fac(sqrtf(s2));
    ya0*=f2; ya1*=f2; yb0*=f2; yb1*=f2;
    x2[t]     = make_float2(ya0, ya1);
    x2[t+256] = make_float2(yb0, yb1);
    xp2[cidx(m, t,     NCKD)] = packh2(ya0, ya1);
    xp2[cidx(m, t+256, NCKD)] = packh2(yb0, yb1);
    GDC_LAUNCH();
}

// ---------------- host ----------------
struct GraphAux {
    cudaStream_t s1;
    cudaEvent_t evRoot, evQ0, evCn1, evO, evQ, evHg, evFo, evLog;
    GraphAux(){
        cudaStreamCreateWithFlags(&s1, cudaStreamNonBlocking);
        cudaEventCreateWithFlags(&evRoot, cudaEventDisableTiming);
        cudaEventCreateWithFlags(&evQ0,   cudaEventDisableTiming);
        cudaEventCreateWithFlags(&evCn1,  cudaEventDisableTiming);
        cudaEventCreateWithFlags(&evO,    cudaEventDisableTiming);
        cudaEventCreateWithFlags(&evQ,    cudaEventDisableTiming);
        cudaEventCreateWithFlags(&evHg,   cudaEventDisableTiming);
        cudaEventCreateWithFlags(&evFo,   cudaEventDisableTiming);
        cudaEventCreateWithFlags(&evLog,  cudaEventDisableTiming);
    }
};
static GraphAux g_aux;

template<typename T> static void* symaddr(T& s){
    void* p = nullptr; cudaGetSymbolAddress(&p, s); return p;
}

template<typename F, typename... Args>
static void pdl(F fn, dim3 gr, dim3 bl, size_t sh, Args... args){
    cudaLaunchConfig_t cfg = {};
    cfg.gridDim = gr; cfg.blockDim = bl; cfg.dynamicSmemBytes = sh; cfg.stream = 0;
    cudaLaunchAttribute at{};
    at.id = cudaLaunchAttributeProgrammaticStreamSerialization;
    at.val.programmaticStreamSerializationAllowed = 1;
    cfg.attrs = &at; cfg.numAttrs = 1;
    cudaLaunchKernelEx(&cfg, fn, args...);
}

extern "C" void kernel_launch(void* const* d_in, const int* in_sizes, int n_in,
                              void* d_out, int out_size){
    (void)in_sizes; (void)n_in; (void)out_size;
    const int*   ids        = (const int*)  d_in[0];
    const float* W_emb      = (const float*)d_in[2];
    const float* Wq         = (const float*)d_in[3];
    const float* Wk         = (const float*)d_in[4];
    const float* Wv         = (const float*)d_in[5];
    const float* Wbeta      = (const float*)d_in[6];
    const float* Wo         = (const float*)d_in[7];
    const float* Wffh       = (const float*)d_in[8];
    const float* Wffg       = (const float*)d_in[9];
    const float* Wffo       = (const float*)d_in[10];
    const float* qk_scale   = (const float*)d_in[11];
    const float* beta_scale = (const float*)d_in[12];
    const float* attn_alpha = (const float*)d_in[13];
    const float* ff_alpha   = (const float*)d_in[14];
    const float* ffh_scale  = (const float*)d_in[15];
    const float* ffg_scale  = (const float*)d_in[16];
    const float* W_logits   = (const float*)d_in[17];
    const float* logit_scale= (const float*)d_in[18];
    float* out = (float*)d_out;

    float* x     = (float*)symaddr(g_x);
    float* qkv   = (float*)symaddr(g_qkv);
    float* obuf  = (float*)symaddr(g_obuf);
    float* v0h   = (float*)symaddr(g_v0h);
    float* fo    = (float*)symaddr(g_fo);
    float* fffo  = (float*)symaddr(g_fffo);
    float* part  = (float*)symaddr(g_part);
    uint32_t* xp2   = (uint32_t*)symaddr(g_xp2);
    uint32_t* op2   = (uint32_t*)symaddr(g_op2);
    uint32_t* zp2   = (uint32_t*)symaddr(g_zp2);
    uint32_t* wqkv2 = (uint32_t*)symaddr(g_wqkv2);
    uint32_t* wo2   = (uint32_t*)symaddr(g_wo2);
    uint32_t* whg2  = (uint32_t*)symaddr(g_whg2);
    uint32_t* wfo2  = (uint32_t*)symaddr(g_wfo2);
    uint32_t* wl2   = (uint32_t*)symaddr(g_wl2);

    cudaFuncSetAttribute(gemm_mma_k<128,128,64,32,3,0>, cudaFuncAttributeMaxDynamicSharedMemorySize, 99328);
    cudaFuncSetAttribute(gemm_hg_k<128,64,32,32,3>,     cudaFuncAttributeMaxDynamicSharedMemorySize, 74752);
    cudaFuncSetAttribute(gemm_mma_k<64,64,32,16,4,0>,   cudaFuncAttributeMaxDynamicSharedMemorySize, 66560);

    cudaStream_t s1 = g_aux.s1;

    cudaEventRecord(g_aux.evRoot, 0);
    cudaStreamWaitEvent(s1, g_aux.evRoot, 0);

    // side stream: earliest-consumer order; layer-0 qkv pack first
    wpack_qkv_k<<<NQKV, 256, 0, s1>>>(Wq, Wk, Wv, 0, wqkv2);
    cudaEventRecord(g_aux.evQ0, s1);
    colnorm_part_k<<<dim3(Dm/256, NL, 8), 256, 0, s1>>>(Wo, part, Dm, Dm);
    colnorm_fin_k<<<dim3(Dm/256, NL), 256, 0, s1>>>(part, fo, Dm);
    cudaEventRecord(g_aux.evCn1, s1);
    wpack_o_k<<<NL*Dm, 256, 0, s1>>>(Wo, wo2);
    cudaEventRecord(g_aux.evO, s1);
    wpack_hg_k<<<NL*NHG, 256, 0, s1>>>(Wffh, Wffg, ffh_scale, ffg_scale, whg2);
    cudaEventRecord(g_aux.evHg, s1);
    wpack_qkv_k<<<3*NQKV, 256, 0, s1>>>(Wq, Wk, Wv, 1, wqkv2);
    cudaEventRecord(g_aux.evQ, s1);
    colnorm_part_k<<<dim3((DFFn+255)/256, NL, 8), 256, 0, s1>>>(Wffo, part, Dm, DFFn);
    colnorm_fin_k<<<dim3((DFFn+255)/256, NL), 256, 0, s1>>>(part, fffo, DFFn);
    wpack_fo_k<<<NL*Dm, 256, 0, s1>>>(Wffo, fffo, wfo2);
    cudaEventRecord(g_aux.evFo, s1);
    wpack_log_k<<<NV, 256, 0, s1>>>(W_logits, logit_scale, wl2);
    cudaEventRecord(g_aux.evLog, s1);

    // main stream (PDL chain)
    pdl(embed_k, dim3(MT), dim3(256), 0, ids, W_emb, x, xp2);

    for(int l=0;l<NL;l++){
        if(l==0) cudaStreamWaitEvent(0, g_aux.evQ0, 0);
        if(l==1) cudaStreamWaitEvent(0, g_aux.evQ, 0);
        pdl(gemm_mma_k<128,128,64,32,3,0>, dim3(8, NQKV/128), dim3(256), 99328,
            (const uint32_t*)xp2, (const uint32_t*)(wqkv2 + (size_t)l*NQKV*UD),
            (void*)qkv, NQKV, Dm);
        if(l==0) cudaStreamWaitEvent(0, g_aux.evCn1, 0);
        pdl(delta_k, dim3(NB*NH), dim3(256), 0,
            (const float*)qkv, (const float*)(qk_scale + l*Dm), Wbeta, beta_scale,
            l, (l==0)?1:0, v0h, op2, (const float*)(fo + l*Dm));
        if(l==0) cudaStreamWaitEvent(0, g_aux.evO, 0);
        pdl(gemm_mma_k<64,64,32,16,4,0>, dim3(16, 16), dim3(256), 66560,
            (const uint32_t*)op2, (const uint32_t*)(wo2 + (size_t)l*Dm*UD),
            (void*)obuf, Dm, Dm);
        pdl(resid_k, dim3(MT), dim3(256), 0,
            x, (const float*)obuf, (const float*)(attn_alpha + l*Dm), xp2);
        if(l==0) cudaStreamWaitEvent(0, g_aux.evHg, 0);
        pdl(gemm_hg_k<128,64,32,32,3>, dim3(8, NHG/64), dim3(256), 74752,
            (const uint32_t*)xp2, (const uint32_t*)(whg2 + (size_t)l*NHG*UD),
            zp2, NCKF, Dm);
        if(l==0) cudaStreamWaitEvent(0, g_aux.evFo, 0);
        pdl(gemm_mma_k<64,64,32,16,4,0>, dim3(16, 16), dim3(256), 66560,
            (const uint32_t*)zp2, (const uint32_t*)(wfo2 + (size_t)l*Dm*UF),
            (void*)obuf, Dm, DFFP);
        pdl(resid_k, dim3(MT), dim3(256), 0,
            x, (const float*)obuf, (const float*)(ff_alpha + l*Dm), xp2);
    }
    cudaStreamWaitEvent(0, g_aux.evLog, 0);
    pdl(gemm_mma_k<128,128,64,32,3,0>, dim3(8, NV/128), dim3(256), 99328,
        (const uint32_t*)xp2, (const uint32_t*)wl2, (void*)out, NV, Dm);
}